// round 1
// baseline (speedup 1.0000x reference)
#include <cuda_runtime.h>
#include <math.h>

#define Bn 256
#define Ln 256
#define Cn 128
#define HIDn 128
#define Nn (Bn*Cn)
#define HSs 132          // padded row stride for 128-wide smem tiles (16B aligned)
#define MAXE 4352        // 4096 edges + 128 self loops, padded

// ---------------- device scratch (no allocs allowed) ----------------
__device__ float g_h[Nn*HIDn];          // 16 MB node features
__device__ int g_cnt[Cn];
__device__ int g_ptr[Cn+1];
__device__ int g_cur[Cn];
__device__ unsigned short g_src[MAXE];
__device__ int g_is64;

// ---------------- CSR build (per-launch, deterministic structure) ----------------
__global__ void k_detect(const int* ei32) {
    // int64 values < 128 => every odd 32-bit word is 0. 32 random samples suffice.
    int v = ei32[threadIdx.x*2 + 1];
    unsigned ball = __ballot_sync(0xffffffffu, v != 0);
    if (threadIdx.x == 0) g_is64 = (ball == 0) ? 1 : 0;
}

__global__ void k_csr_init() { g_cnt[threadIdx.x] = 1; }  // self loop

__device__ __forceinline__ int edge_val(const void* ei, int idx) {
    if (g_is64) return (int)((const long long*)ei)[idx];
    return ((const int*)ei)[idx];
}

__global__ void k_csr_count(const void* ei, int E) {
    int e = blockIdx.x*blockDim.x + threadIdx.x;
    if (e < E) {
        int d = edge_val(ei, E + e);
        atomicAdd(&g_cnt[d], 1);
    }
}

__global__ void k_csr_scan() {
    if (threadIdx.x == 0) {
        int s = 0;
        for (int i = 0; i < Cn; i++) { g_ptr[i] = s; s += g_cnt[i]; }
        g_ptr[Cn] = s;
    }
    __syncthreads();
    g_cur[threadIdx.x] = g_ptr[threadIdx.x];
}

__global__ void k_csr_fill(const void* ei, int E) {
    int e = blockIdx.x*blockDim.x + threadIdx.x;
    if (e < E) {
        int s = edge_val(ei, e);
        int d = edge_val(ei, E + e);
        int p = atomicAdd(&g_cur[d], 1);
        g_src[p] = (unsigned short)s;
    } else if (e < E + Cn) {
        int c = e - E;
        int p = atomicAdd(&g_cur[c], 1);
        g_src[p] = (unsigned short)c;
    }
}

// ---------------- embedding: h[b*C+c][j] = sum_l x[b,l,c] * W[l,j] + bias[j] ----------------
__global__ void __launch_bounds__(256) k_embed(const float* __restrict__ x,
                                               const float* __restrict__ W,
                                               const float* __restrict__ bias) {
    __shared__ float xs[32*128];
    __shared__ float ws[32*128];
    int b = blockIdx.x, tid = threadIdx.x;
    int ty = tid >> 4, tx = tid & 15;
    int c0 = ty*8, j0 = tx*8;
    float acc[8][8];
#pragma unroll
    for (int i = 0; i < 8; i++)
#pragma unroll
        for (int j = 0; j < 8; j++) acc[i][j] = 0.f;

    const float* xb = x + (size_t)b*Ln*Cn;
    for (int l0 = 0; l0 < Ln; l0 += 32) {
        for (int i = tid; i < 32*128/4; i += 256) {
            ((float4*)xs)[i] = ((const float4*)(xb + l0*Cn))[i];
            ((float4*)ws)[i] = ((const float4*)(W + l0*HIDn))[i];
        }
        __syncthreads();
#pragma unroll 8
        for (int l = 0; l < 32; l++) {
            float4 a0 = *(const float4*)(xs + l*128 + c0);
            float4 a1 = *(const float4*)(xs + l*128 + c0 + 4);
            float4 b0 = *(const float4*)(ws + l*128 + j0);
            float4 b1 = *(const float4*)(ws + l*128 + j0 + 4);
            float av[8] = {a0.x,a0.y,a0.z,a0.w,a1.x,a1.y,a1.z,a1.w};
            float bv[8] = {b0.x,b0.y,b0.z,b0.w,b1.x,b1.y,b1.z,b1.w};
#pragma unroll
            for (int i = 0; i < 8; i++)
#pragma unroll
                for (int j = 0; j < 8; j++) acc[i][j] += av[i]*bv[j];
        }
        __syncthreads();
    }
#pragma unroll
    for (int i = 0; i < 8; i++) {
#pragma unroll
        for (int j = 0; j < 8; j++)
            g_h[((size_t)b*Cn + c0 + i)*HIDn + j0 + j] = acc[i][j] + bias[j0 + j];
    }
}

// ---------------- fused GAT layer: 2 GEMMs + softmax agg + ELU + residual + LN ----------------
__global__ void __launch_bounds__(256) k_layer(
    const float* __restrict__ Wl, const float* __restrict__ bl,
    const float* __restrict__ Wr, const float* __restrict__ br,
    const float* __restrict__ att, const float* __restrict__ gbias,
    const float* __restrict__ gamma, const float* __restrict__ beta,
    float* attn_out, int nE) {

    extern __shared__ float smem[];
    float* hs  = smem;                  // 128 x HSs
    float* xls = hs  + Cn*HSs;
    float* xrs = xls + Cn*HSs;
    float* ws  = xrs + Cn*HSs;          // 32 x 128 staging
    int* sptr = (int*)(ws + 32*128);    // 129 (+pad to 132)
    unsigned short* ssrc = (unsigned short*)(sptr + 132);

    int b = blockIdx.x, tid = threadIdx.x;

    // load h graph + CSR
    const float4* hg = (const float4*)(g_h + (size_t)b*Cn*HIDn);
    for (int i = tid; i < Cn*HIDn/4; i += 256) {
        int r = i >> 5, cc = i & 31;
        *(float4*)(hs + r*HSs + cc*4) = hg[i];
    }
    for (int i = tid; i <= Cn; i += 256) sptr[i] = g_ptr[i];
    for (int i = tid; i < nE; i += 256) ssrc[i] = g_src[i];
    __syncthreads();

    int ty = tid >> 4, tx = tid & 15;
    int c0 = ty*8, j0 = tx*8;

    // ---- GEMM: xl = h @ Wl + bl ----
    {
        float acc[8][8];
#pragma unroll
        for (int i=0;i<8;i++)
#pragma unroll
            for (int j=0;j<8;j++) acc[i][j]=0.f;
        for (int k0 = 0; k0 < 128; k0 += 32) {
            for (int i = tid; i < 1024; i += 256)
                ((float4*)ws)[i] = ((const float4*)(Wl + k0*128))[i];
            __syncthreads();
#pragma unroll 8
            for (int kk = 0; kk < 32; kk++) {
                float a[8];
#pragma unroll
                for (int i = 0; i < 8; i++) a[i] = hs[(c0+i)*HSs + k0+kk];
                float4 b0 = *(const float4*)(ws + kk*128 + j0);
                float4 b1 = *(const float4*)(ws + kk*128 + j0 + 4);
                float bv[8] = {b0.x,b0.y,b0.z,b0.w,b1.x,b1.y,b1.z,b1.w};
#pragma unroll
                for (int i = 0; i < 8; i++)
#pragma unroll
                    for (int j = 0; j < 8; j++) acc[i][j] += a[i]*bv[j];
            }
            __syncthreads();
        }
#pragma unroll
        for (int i = 0; i < 8; i++)
#pragma unroll
            for (int j = 0; j < 8; j++)
                xls[(c0+i)*HSs + j0+j] = acc[i][j] + bl[j0+j];
    }
    // ---- GEMM: xr = h @ Wr + br ----
    {
        float acc[8][8];
#pragma unroll
        for (int i=0;i<8;i++)
#pragma unroll
            for (int j=0;j<8;j++) acc[i][j]=0.f;
        for (int k0 = 0; k0 < 128; k0 += 32) {
            for (int i = tid; i < 1024; i += 256)
                ((float4*)ws)[i] = ((const float4*)(Wr + k0*128))[i];
            __syncthreads();
#pragma unroll 8
            for (int kk = 0; kk < 32; kk++) {
                float a[8];
#pragma unroll
                for (int i = 0; i < 8; i++) a[i] = hs[(c0+i)*HSs + k0+kk];
                float4 b0 = *(const float4*)(ws + kk*128 + j0);
                float4 b1 = *(const float4*)(ws + kk*128 + j0 + 4);
                float bv[8] = {b0.x,b0.y,b0.z,b0.w,b1.x,b1.y,b1.z,b1.w};
#pragma unroll
                for (int i = 0; i < 8; i++)
#pragma unroll
                    for (int j = 0; j < 8; j++) acc[i][j] += a[i]*bv[j];
            }
            __syncthreads();
        }
#pragma unroll
        for (int i = 0; i < 8; i++)
#pragma unroll
            for (int j = 0; j < 8; j++)
                xrs[(c0+i)*HSs + j0+j] = acc[i][j] + br[j0+j];
    }
    __syncthreads();

    // ---- edge softmax aggregation ----
    // lane owns k = 4*lane .. 4*lane+3 ; head = lane>>3 ; logit reduce = 3 shfl within 8 lanes
    int warp = tid >> 5, lane = tid & 31;
    int hh = lane >> 3;
    int k4 = lane * 4;
    float4 a4 = *(const float4*)(att + hh*32 + (lane & 7)*4);

    for (int c = warp; c < Cn; c += 8) {
        int e0 = sptr[c], e1 = sptr[c+1];
        float4 xr4 = *(const float4*)(xrs + c*HSs + k4);
        float m = -1e30f;
        for (int e = e0; e < e1; e++) {
            int s = ssrc[e];
            float4 x4 = *(const float4*)(xls + s*HSs + k4);
            float t0 = x4.x + xr4.x; t0 = t0 > 0.f ? t0 : 0.2f*t0;
            float t1 = x4.y + xr4.y; t1 = t1 > 0.f ? t1 : 0.2f*t1;
            float t2 = x4.z + xr4.z; t2 = t2 > 0.f ? t2 : 0.2f*t2;
            float t3 = x4.w + xr4.w; t3 = t3 > 0.f ? t3 : 0.2f*t3;
            float v = t0*a4.x + t1*a4.y + t2*a4.z + t3*a4.w;
            v += __shfl_xor_sync(0xffffffffu, v, 1);
            v += __shfl_xor_sync(0xffffffffu, v, 2);
            v += __shfl_xor_sync(0xffffffffu, v, 4);
            m = fmaxf(m, v);
        }
        float sp = 0.f;
        float4 acc = {0.f,0.f,0.f,0.f};
        for (int e = e0; e < e1; e++) {
            int s = ssrc[e];
            float4 x4 = *(const float4*)(xls + s*HSs + k4);
            float t0 = x4.x + xr4.x; t0 = t0 > 0.f ? t0 : 0.2f*t0;
            float t1 = x4.y + xr4.y; t1 = t1 > 0.f ? t1 : 0.2f*t1;
            float t2 = x4.z + xr4.z; t2 = t2 > 0.f ? t2 : 0.2f*t2;
            float t3 = x4.w + xr4.w; t3 = t3 > 0.f ? t3 : 0.2f*t3;
            float v = t0*a4.x + t1*a4.y + t2*a4.z + t3*a4.w;
            v += __shfl_xor_sync(0xffffffffu, v, 1);
            v += __shfl_xor_sync(0xffffffffu, v, 2);
            v += __shfl_xor_sync(0xffffffffu, v, 4);
            float p = __expf(v - m);
            sp += p;
            acc.x += p*x4.x; acc.y += p*x4.y; acc.z += p*x4.z; acc.w += p*x4.w;
        }
        float inv = 1.0f / (sp + 1e-16f);

        // epilogue: +gat_bias, ELU, residual, LayerNorm
        float4 gb4 = *(const float4*)(gbias + k4);
        float4 h4  = *(const float4*)(hs + c*HSs + k4);
        float val[4];
        {
            float o;
            o = acc.x*inv + gb4.x; o = o > 0.f ? o : expm1f(o); val[0] = h4.x + o;
            o = acc.y*inv + gb4.y; o = o > 0.f ? o : expm1f(o); val[1] = h4.y + o;
            o = acc.z*inv + gb4.z; o = o > 0.f ? o : expm1f(o); val[2] = h4.z + o;
            o = acc.w*inv + gb4.w; o = o > 0.f ? o : expm1f(o); val[3] = h4.w + o;
        }
        float s1 = val[0]+val[1]+val[2]+val[3];
#pragma unroll
        for (int off = 16; off; off >>= 1) s1 += __shfl_xor_sync(0xffffffffu, s1, off);
        float mu = s1 * (1.0f/128.0f);
        float d0 = val[0]-mu, d1 = val[1]-mu, d2 = val[2]-mu, d3 = val[3]-mu;
        float s2 = d0*d0 + d1*d1 + d2*d2 + d3*d3;
#pragma unroll
        for (int off = 16; off; off >>= 1) s2 += __shfl_xor_sync(0xffffffffu, s2, off);
        float rs = rsqrtf(s2 * (1.0f/128.0f) + 1e-5f);
        float4 g4  = *(const float4*)(gamma + k4);
        float4 be4 = *(const float4*)(beta + k4);
        float4 outv;
        outv.x = d0*rs*g4.x + be4.x;
        outv.y = d1*rs*g4.y + be4.y;
        outv.z = d2*rs*g4.z + be4.z;
        outv.w = d3*rs*g4.w + be4.w;
        *(float4*)(g_h + ((size_t)b*Cn + c)*HIDn + k4) = outv;

        // attention map (last layer only): attn[b, dst, src] += mean_h(alpha)
        if (attn_out) {
            float* row = attn_out + (size_t)b*Cn*Cn + (size_t)c*Cn;
            for (int e = e0; e < e1; e++) {
                int s = ssrc[e];
                float4 x4 = *(const float4*)(xls + s*HSs + k4);
                float t0 = x4.x + xr4.x; t0 = t0 > 0.f ? t0 : 0.2f*t0;
                float t1 = x4.y + xr4.y; t1 = t1 > 0.f ? t1 : 0.2f*t1;
                float t2 = x4.z + xr4.z; t2 = t2 > 0.f ? t2 : 0.2f*t2;
                float t3 = x4.w + xr4.w; t3 = t3 > 0.f ? t3 : 0.2f*t3;
                float v = t0*a4.x + t1*a4.y + t2*a4.z + t3*a4.w;
                v += __shfl_xor_sync(0xffffffffu, v, 1);
                v += __shfl_xor_sync(0xffffffffu, v, 2);
                v += __shfl_xor_sync(0xffffffffu, v, 4);
                float am = __expf(v - m) * inv;        // alpha for this lane's head
                am += __shfl_xor_sync(0xffffffffu, am, 8);
                am += __shfl_xor_sync(0xffffffffu, am, 16);
                if (lane == 0) row[s] += am * 0.25f;
            }
        }
    }
}

// ---------------- projection: out[b,l,c] = sum_j h[b*C+c][j] * W[j][l] + bias[l] ----------------
__global__ void __launch_bounds__(256) k_proj(const float* __restrict__ W,
                                              const float* __restrict__ bias,
                                              float* __restrict__ out) {
    extern __shared__ float smem[];
    float* hs = smem;             // 128 x HSs
    float* ws = hs + Cn*HSs;      // 32 x 128
    int b = blockIdx.x, tid = threadIdx.x;

    const float4* hg = (const float4*)(g_h + (size_t)b*Cn*HIDn);
    for (int i = tid; i < Cn*HIDn/4; i += 256) {
        int r = i >> 5, cc = i & 31;
        *(float4*)(hs + r*HSs + cc*4) = hg[i];
    }
    __syncthreads();

    int ty = tid >> 4, tx = tid & 15;
    int c0 = ty*8, l0 = tx*8;
    for (int lh = 0; lh < 2; lh++) {
        float acc[8][8];
#pragma unroll
        for (int i=0;i<8;i++)
#pragma unroll
            for (int j=0;j<8;j++) acc[i][j]=0.f;
        for (int k0 = 0; k0 < 128; k0 += 32) {
            for (int i = tid; i < 1024; i += 256) {
                int kk = i >> 5, col4 = (i & 31);
                *(float4*)(ws + kk*128 + col4*4) =
                    *(const float4*)(W + (size_t)(k0+kk)*Ln + lh*128 + col4*4);
            }
            __syncthreads();
#pragma unroll 8
            for (int kk = 0; kk < 32; kk++) {
                float a[8];
#pragma unroll
                for (int i = 0; i < 8; i++) a[i] = hs[(c0+i)*HSs + k0+kk];
                float4 b0 = *(const float4*)(ws + kk*128 + l0);
                float4 b1 = *(const float4*)(ws + kk*128 + l0 + 4);
                float bv[8] = {b0.x,b0.y,b0.z,b0.w,b1.x,b1.y,b1.z,b1.w};
#pragma unroll
                for (int i = 0; i < 8; i++)
#pragma unroll
                    for (int j = 0; j < 8; j++) acc[i][j] += a[i]*bv[j];
            }
            __syncthreads();
        }
        // write out[b, l, c0..c0+7] — c contiguous
#pragma unroll
        for (int j = 0; j < 8; j++) {
            int l = lh*128 + l0 + j;
            float pb = bias[l];
            float4 v0 = {acc[0][j]+pb, acc[1][j]+pb, acc[2][j]+pb, acc[3][j]+pb};
            float4 v1 = {acc[4][j]+pb, acc[5][j]+pb, acc[6][j]+pb, acc[7][j]+pb};
            float* dst = out + (size_t)b*Ln*Cn + (size_t)l*Cn + c0;
            *(float4*)dst = v0;
            *(float4*)(dst + 4) = v1;
        }
    }
}

// ---------------- launch ----------------
extern "C" void kernel_launch(void* const* d_in, const int* in_sizes, int n_in,
                              void* d_out, int out_size) {
    const float* x    = (const float*)d_in[0];
    const void*  ei   = d_in[1];
    const float* embW = (const float*)d_in[2];
    const float* embB = (const float*)d_in[3];
    const float* WlA  = (const float*)d_in[4];
    const float* blA  = (const float*)d_in[5];
    const float* WrA  = (const float*)d_in[6];
    const float* brA  = (const float*)d_in[7];
    const float* attA = (const float*)d_in[8];
    const float* gbA  = (const float*)d_in[9];
    const float* gA   = (const float*)d_in[10];
    const float* beA  = (const float*)d_in[11];
    const float* pW   = (const float*)d_in[12];
    const float* pB   = (const float*)d_in[13];
    float* out = (float*)d_out;

    int E = in_sizes[1] / 2;
    int nE = E + Cn;
    if (nE > MAXE) nE = MAXE;

    const int SMEM_LAYER = (3*Cn*HSs + 32*128)*(int)sizeof(float)
                         + 132*(int)sizeof(int) + MAXE*(int)sizeof(unsigned short);
    const int SMEM_PROJ  = (Cn*HSs + 32*128)*(int)sizeof(float);

    cudaFuncSetAttribute(k_layer, cudaFuncAttributeMaxDynamicSharedMemorySize, SMEM_LAYER);
    cudaFuncSetAttribute(k_proj,  cudaFuncAttributeMaxDynamicSharedMemorySize, SMEM_PROJ);

    k_detect<<<1, 32>>>((const int*)ei);
    k_csr_init<<<1, Cn>>>();
    k_csr_count<<<(E + 255)/256, 256>>>(ei, E);
    k_csr_scan<<<1, Cn>>>();
    k_csr_fill<<<(E + Cn + 255)/256, 256>>>(ei, E);

    k_embed<<<Bn, 256>>>(x, embW, embB);

    // layer 0 (no attention map)
    k_layer<<<Bn, 256, SMEM_LAYER>>>(WlA, blA, WrA, brA, attA, gbA, gA, beA,
                                     nullptr, nE);

    // zero attention-map region, then layer 1 accumulates into it
    float* attn = out + (size_t)Bn*Ln*Cn;
    cudaMemsetAsync(attn, 0, (size_t)Bn*Cn*Cn*sizeof(float));
    k_layer<<<Bn, 256, SMEM_LAYER>>>(WlA + HIDn*HIDn, blA + HIDn,
                                     WrA + HIDn*HIDn, brA + HIDn,
                                     attA + 4*32, gbA + HIDn, gA + HIDn, beA + HIDn,
                                     attn, nE);

    k_proj<<<Bn, 256, SMEM_PROJ>>>(pW, pB, out);
}

// round 3
// speedup vs baseline: 1.6077x; 1.6077x over previous
#include <cuda_runtime.h>
#include <math.h>

#define Bn 256
#define Ln 256
#define Cn 128
#define HIDn 128
#define MAXE 4352        // 4096 edges + 128 self loops

// ---------------- device scratch (no allocs allowed) ----------------
__device__ int g_ptr[Cn + 1];
__device__ unsigned short g_src[MAXE];

// ---------------- single-kernel CSR build ----------------
__global__ void k_csr(const void* ei, int E) {
    __shared__ int cnt[Cn];
    __shared__ int base[Cn + 1];
    __shared__ int is64s;
    int tid = threadIdx.x;

    if (tid < 32) {
        int v = ((const int*)ei)[tid * 2 + 1];
        unsigned ball = __ballot_sync(0xffffffffu, v != 0);
        if (tid == 0) is64s = (ball == 0) ? 1 : 0;
    }
    if (tid < Cn) cnt[tid] = 1;              // self loop
    __syncthreads();
    int is64 = is64s;

    for (int e = tid; e < E; e += blockDim.x) {
        int d = is64 ? (int)((const long long*)ei)[E + e] : ((const int*)ei)[E + e];
        atomicAdd(&cnt[d], 1);
    }
    __syncthreads();

    if (tid < 32) {  // warp scan: 4 counts per lane
        int c0 = cnt[tid*4], c1 = cnt[tid*4+1], c2 = cnt[tid*4+2], c3 = cnt[tid*4+3];
        int s = c0 + c1 + c2 + c3;
        int pre = s;
#pragma unroll
        for (int off = 1; off < 32; off <<= 1) {
            int t = __shfl_up_sync(0xffffffffu, pre, off);
            if (tid >= off) pre += t;
        }
        int excl = pre - s;
        base[tid*4]     = excl;
        base[tid*4 + 1] = excl + c0;
        base[tid*4 + 2] = excl + c0 + c1;
        base[tid*4 + 3] = excl + c0 + c1 + c2;
        if (tid == 31) base[Cn] = pre;
    }
    __syncthreads();
    if (tid <= Cn) g_ptr[tid] = base[tid];
    if (tid < Cn) cnt[tid] = base[tid];      // reuse as cursor
    __syncthreads();

    for (int e = tid; e < E; e += blockDim.x) {
        int s = is64 ? (int)((const long long*)ei)[e]     : ((const int*)ei)[e];
        int d = is64 ? (int)((const long long*)ei)[E + e] : ((const int*)ei)[E + e];
        int p = atomicAdd(&cnt[d], 1);
        g_src[p] = (unsigned short)s;
    }
    __syncthreads();
    if (tid < Cn) {                           // self loop entries
        int p = atomicAdd(&cnt[tid], 1);
        g_src[p] = (unsigned short)tid;
    }
}

// ---------------- GEMM helper: Osm[128x128] = Asm[128x128] @ Wg[128x128] + bias ----------------
__device__ __forceinline__ void gemm128(const float* __restrict__ Asm,
                                        const float* __restrict__ Wg,
                                        const float* __restrict__ bias,
                                        float* __restrict__ Osm,
                                        float* __restrict__ stage,
                                        int tid, int c0, int j0) {
    float acc[8][8];
#pragma unroll
    for (int i = 0; i < 8; i++)
#pragma unroll
        for (int j = 0; j < 8; j++) acc[i][j] = 0.f;

    for (int k0 = 0; k0 < 128; k0 += 32) {
        __syncthreads();
        for (int i = tid; i < 1024; i += 256)
            ((float4*)stage)[i] = ((const float4*)(Wg + k0 * 128))[i];
        __syncthreads();
#pragma unroll 8
        for (int kk = 0; kk < 32; kk++) {
            float a[8];
#pragma unroll
            for (int i = 0; i < 8; i++) a[i] = Asm[(c0 + i) * 128 + k0 + kk];
            float4 b0 = *(const float4*)(stage + kk * 128 + j0);
            float4 b1 = *(const float4*)(stage + kk * 128 + j0 + 4);
            float bv[8] = {b0.x, b0.y, b0.z, b0.w, b1.x, b1.y, b1.z, b1.w};
#pragma unroll
            for (int i = 0; i < 8; i++)
#pragma unroll
                for (int j = 0; j < 8; j++) acc[i][j] += a[i] * bv[j];
        }
    }
    float4 bb0 = *(const float4*)(bias + j0);
    float4 bb1 = *(const float4*)(bias + j0 + 4);
#pragma unroll
    for (int i = 0; i < 8; i++) {
        float4 v0 = {acc[i][0] + bb0.x, acc[i][1] + bb0.y, acc[i][2] + bb0.z, acc[i][3] + bb0.w};
        float4 v1 = {acc[i][4] + bb1.x, acc[i][5] + bb1.y, acc[i][6] + bb1.z, acc[i][7] + bb1.w};
        *(float4*)(Osm + (c0 + i) * 128 + j0) = v0;
        *(float4*)(Osm + (c0 + i) * 128 + j0 + 4) = v1;
    }
}

// ---------------- GAT layer (GEMMs + single-pass softmax agg + ELU + residual + LN) ----------------
// ATT: rowbuf = per-warp 512 floats (4 heads x 128 sources), unnormalized p
// accumulated PER HEAD; final attn row = 0.25 * sum_h rb[h][s] * inv_h.
template <bool ATT>
__device__ __forceinline__ void gat_layer(
    float* hs, float* xls, float* xrs, float* stage,
    const int* sptr, const unsigned short* ssrc,
    const float* __restrict__ Wl, const float* __restrict__ bl,
    const float* __restrict__ Wr, const float* __restrict__ br,
    const float* __restrict__ att, const float* __restrict__ gbias,
    const float* __restrict__ gamma, const float* __restrict__ beta,
    float* attn_rows, int tid) {

    int c0 = (tid >> 4) * 8, j0 = (tid & 15) * 8;
    gemm128(hs, Wl, bl, xls, stage, tid, c0, j0);
    gemm128(hs, Wr, br, xrs, stage, tid, c0, j0);
    __syncthreads();

    int warp = tid >> 5, lane = tid & 31;
    int hh = lane >> 3;
    int k4 = lane * 4;
    float4 a4 = *(const float4*)(att + hh * 32 + (lane & 7) * 4);
    float* rb = stage + warp * 512;      // stage idle during aggregation; 8*512 = 4096 fits
    bool headrep = ((lane & 7) == 0);    // lanes 0,8,16,24 — one per head

    for (int c = warp; c < Cn; c += 8) {
        int e0 = sptr[c], e1 = sptr[c + 1];
        float4 xr4 = *(const float4*)(xrs + c * 128 + k4);
        if (ATT) {
            // zero the 4 per-head rows (512 floats, 4 float4 per lane)
#pragma unroll
            for (int h = 0; h < 4; h++)
                *(float4*)(rb + h * 128 + k4) = make_float4(0.f, 0.f, 0.f, 0.f);
            __syncwarp();
        }
        float sp = 0.f;
        float4 acc = make_float4(0.f, 0.f, 0.f, 0.f);
        // single pass: no max-shift needed — logits are O(1) by construction
#pragma unroll 2
        for (int e = e0; e < e1; e++) {
            int s = ssrc[e];
            float4 x4 = *(const float4*)(xls + s * 128 + k4);
            float t0 = x4.x + xr4.x; t0 = t0 > 0.f ? t0 : 0.2f * t0;
            float t1 = x4.y + xr4.y; t1 = t1 > 0.f ? t1 : 0.2f * t1;
            float t2 = x4.z + xr4.z; t2 = t2 > 0.f ? t2 : 0.2f * t2;
            float t3 = x4.w + xr4.w; t3 = t3 > 0.f ? t3 : 0.2f * t3;
            float v = t0 * a4.x + t1 * a4.y + t2 * a4.z + t3 * a4.w;
            v += __shfl_xor_sync(0xffffffffu, v, 1);
            v += __shfl_xor_sync(0xffffffffu, v, 2);
            v += __shfl_xor_sync(0xffffffffu, v, 4);
            float p = __expf(v);
            sp += p;
            acc.x += p * x4.x; acc.y += p * x4.y; acc.z += p * x4.z; acc.w += p * x4.w;
            if (ATT) {
                if (headrep) rb[hh * 128 + s] += p;   // per-head unnormalized
            }
        }
        float inv = 1.0f / (sp + 1e-16f);

        // epilogue: +gat_bias, ELU, residual, LayerNorm (in-place into hs)
        float4 gb4 = *(const float4*)(gbias + k4);
        float4 h4 = *(const float4*)(hs + c * 128 + k4);
        float val[4];
        {
            float o;
            o = acc.x * inv + gb4.x; o = o > 0.f ? o : expm1f(o); val[0] = h4.x + o;
            o = acc.y * inv + gb4.y; o = o > 0.f ? o : expm1f(o); val[1] = h4.y + o;
            o = acc.z * inv + gb4.z; o = o > 0.f ? o : expm1f(o); val[2] = h4.z + o;
            o = acc.w * inv + gb4.w; o = o > 0.f ? o : expm1f(o); val[3] = h4.w + o;
        }
        float s1 = val[0] + val[1] + val[2] + val[3];
#pragma unroll
        for (int off = 16; off; off >>= 1) s1 += __shfl_xor_sync(0xffffffffu, s1, off);
        float mu = s1 * (1.0f / 128.0f);
        float d0 = val[0] - mu, d1 = val[1] - mu, d2 = val[2] - mu, d3 = val[3] - mu;
        float s2 = d0 * d0 + d1 * d1 + d2 * d2 + d3 * d3;
#pragma unroll
        for (int off = 16; off; off >>= 1) s2 += __shfl_xor_sync(0xffffffffu, s2, off);
        float rs = rsqrtf(s2 * (1.0f / 128.0f) + 1e-5f);
        float4 g4 = *(const float4*)(gamma + k4);
        float4 be4 = *(const float4*)(beta + k4);
        float4 outv;
        outv.x = d0 * rs * g4.x + be4.x;
        outv.y = d1 * rs * g4.y + be4.y;
        outv.z = d2 * rs * g4.z + be4.z;
        outv.w = d3 * rs * g4.w + be4.w;
        *(float4*)(hs + c * 128 + k4) = outv;

        if (ATT) {
            __syncwarp();
            // broadcast each head's 1/denominator, then per-head normalize + mean
            float i0 = __shfl_sync(0xffffffffu, inv, 0);
            float i1 = __shfl_sync(0xffffffffu, inv, 8);
            float i2 = __shfl_sync(0xffffffffu, inv, 16);
            float i3 = __shfl_sync(0xffffffffu, inv, 24);
            float4 r0 = *(const float4*)(rb + 0 * 128 + k4);
            float4 r1 = *(const float4*)(rb + 1 * 128 + k4);
            float4 r2 = *(const float4*)(rb + 2 * 128 + k4);
            float4 r3 = *(const float4*)(rb + 3 * 128 + k4);
            float4 r;
            r.x = 0.25f * (r0.x * i0 + r1.x * i1 + r2.x * i2 + r3.x * i3);
            r.y = 0.25f * (r0.y * i0 + r1.y * i1 + r2.y * i2 + r3.y * i3);
            r.z = 0.25f * (r0.z * i0 + r1.z * i1 + r2.z * i2 + r3.z * i3);
            r.w = 0.25f * (r0.w * i0 + r1.w * i1 + r2.w * i2 + r3.w * i3);
            *(float4*)(attn_rows + (size_t)c * 128 + k4) = r;
        }
    }
    __syncthreads();
}

// ---------------- fully fused: embed -> layer0 -> layer1(+attn) -> proj ----------------
__global__ void __launch_bounds__(256) k_fused(
    const float* __restrict__ x,
    const float* __restrict__ embW, const float* __restrict__ embB,
    const float* __restrict__ WlA, const float* __restrict__ blA,
    const float* __restrict__ WrA, const float* __restrict__ brA,
    const float* __restrict__ attA, const float* __restrict__ gbA,
    const float* __restrict__ gA, const float* __restrict__ beA,
    const float* __restrict__ pW, const float* __restrict__ pB,
    float* __restrict__ out, int nE) {

    extern __shared__ float smem[];
    float* hs = smem;                    // 128*128
    float* xls = hs + 16384;
    float* xrs = xls + 16384;
    float* stage = xrs + 16384;          // 4096 floats (32x128; doubles as attn rowbuf)
    int* sptr = (int*)(stage + 4096);    // 132 ints
    unsigned short* ssrc = (unsigned short*)(sptr + 132);

    int b = blockIdx.x, tid = threadIdx.x;
    int c0 = (tid >> 4) * 8, j0 = (tid & 15) * 8;

    for (int i = tid; i <= Cn; i += 256) sptr[i] = g_ptr[i];
    for (int i = tid; i < nE; i += 256) ssrc[i] = g_src[i];

    // ---- embed: hs[c][j] = sum_l x[b,l,c] * embW[l,j] + embB[j], K = 256, tiles of 16
    {
        float acc[8][8];
#pragma unroll
        for (int i = 0; i < 8; i++)
#pragma unroll
            for (int j = 0; j < 8; j++) acc[i][j] = 0.f;
        const float* xb = x + (size_t)b * Ln * Cn;
        float* xs = stage;           // 16x128
        float* wstage = stage + 2048;
        for (int l0 = 0; l0 < Ln; l0 += 16) {
            __syncthreads();
            for (int i = tid; i < 512; i += 256) {
                ((float4*)xs)[i] = ((const float4*)(xb + (size_t)l0 * Cn))[i];
                ((float4*)wstage)[i] = ((const float4*)(embW + (size_t)l0 * HIDn))[i];
            }
            __syncthreads();
#pragma unroll 8
            for (int l = 0; l < 16; l++) {
                float4 a0 = *(const float4*)(xs + l * 128 + c0);
                float4 a1 = *(const float4*)(xs + l * 128 + c0 + 4);
                float4 b0 = *(const float4*)(wstage + l * 128 + j0);
                float4 b1 = *(const float4*)(wstage + l * 128 + j0 + 4);
                float av[8] = {a0.x, a0.y, a0.z, a0.w, a1.x, a1.y, a1.z, a1.w};
                float bv[8] = {b0.x, b0.y, b0.z, b0.w, b1.x, b1.y, b1.z, b1.w};
#pragma unroll
                for (int i = 0; i < 8; i++)
#pragma unroll
                    for (int j = 0; j < 8; j++) acc[i][j] += av[i] * bv[j];
            }
        }
        float4 eb0 = *(const float4*)(embB + j0);
        float4 eb1 = *(const float4*)(embB + j0 + 4);
#pragma unroll
        for (int i = 0; i < 8; i++) {
            float4 v0 = {acc[i][0] + eb0.x, acc[i][1] + eb0.y, acc[i][2] + eb0.z, acc[i][3] + eb0.w};
            float4 v1 = {acc[i][4] + eb1.x, acc[i][5] + eb1.y, acc[i][6] + eb1.z, acc[i][7] + eb1.w};
            *(float4*)(hs + (c0 + i) * 128 + j0) = v0;
            *(float4*)(hs + (c0 + i) * 128 + j0 + 4) = v1;
        }
    }
    // (gemm128's leading __syncthreads orders hs writes before reads)

    float* attn = out + (size_t)Bn * Ln * Cn + (size_t)b * Cn * Cn;
    gat_layer<false>(hs, xls, xrs, stage, sptr, ssrc,
                     WlA, blA, WrA, brA, attA, gbA, gA, beA, nullptr, tid);
    gat_layer<true>(hs, xls, xrs, stage, sptr, ssrc,
                    WlA + HIDn * HIDn, blA + HIDn, WrA + HIDn * HIDn, brA + HIDn,
                    attA + 128, gbA + HIDn, gA + HIDn, beA + HIDn, attn, tid);

    // ---- proj: out[b,l,c] = sum_j hs[c][j] * pW[j][l] + pB[l]
    for (int lh = 0; lh < 2; lh++) {
        float acc[8][8];
#pragma unroll
        for (int i = 0; i < 8; i++)
#pragma unroll
            for (int j = 0; j < 8; j++) acc[i][j] = 0.f;
        for (int k0 = 0; k0 < 128; k0 += 32) {
            __syncthreads();
            for (int i = tid; i < 1024; i += 256) {
                int kk = i >> 5, c4 = i & 31;
                *(float4*)(stage + kk * 128 + c4 * 4) =
                    *(const float4*)(pW + (size_t)(k0 + kk) * Ln + lh * 128 + c4 * 4);
            }
            __syncthreads();
#pragma unroll 8
            for (int kk = 0; kk < 32; kk++) {
                float a[8];
#pragma unroll
                for (int i = 0; i < 8; i++) a[i] = hs[(c0 + i) * 128 + k0 + kk];
                float4 b0 = *(const float4*)(stage + kk * 128 + j0);
                float4 b1 = *(const float4*)(stage + kk * 128 + j0 + 4);
                float bv[8] = {b0.x, b0.y, b0.z, b0.w, b1.x, b1.y, b1.z, b1.w};
#pragma unroll
                for (int i = 0; i < 8; i++)
#pragma unroll
                    for (int j = 0; j < 8; j++) acc[i][j] += a[i] * bv[j];
            }
        }
#pragma unroll
        for (int j = 0; j < 8; j++) {
            int l = lh * 128 + j0 + j;
            float pb = pB[l];
            float4 v0 = {acc[0][j] + pb, acc[1][j] + pb, acc[2][j] + pb, acc[3][j] + pb};
            float4 v1 = {acc[4][j] + pb, acc[5][j] + pb, acc[6][j] + pb, acc[7][j] + pb};
            float* dst = out + (size_t)b * Ln * Cn + (size_t)l * Cn + c0;
            *(float4*)dst = v0;
            *(float4*)(dst + 4) = v1;
        }
    }
}

// ---------------- launch ----------------
extern "C" void kernel_launch(void* const* d_in, const int* in_sizes, int n_in,
                              void* d_out, int out_size) {
    const float* x    = (const float*)d_in[0];
    const void*  ei   = d_in[1];
    const float* embW = (const float*)d_in[2];
    const float* embB = (const float*)d_in[3];
    const float* WlA  = (const float*)d_in[4];
    const float* blA  = (const float*)d_in[5];
    const float* WrA  = (const float*)d_in[6];
    const float* brA  = (const float*)d_in[7];
    const float* attA = (const float*)d_in[8];
    const float* gbA  = (const float*)d_in[9];
    const float* gA   = (const float*)d_in[10];
    const float* beA  = (const float*)d_in[11];
    const float* pW   = (const float*)d_in[12];
    const float* pB   = (const float*)d_in[13];
    float* out = (float*)d_out;

    int E = in_sizes[1] / 2;
    int nE = E + Cn;
    if (nE > MAXE) nE = MAXE;

    const int SMEM = (3 * 16384 + 4096) * (int)sizeof(float)
                   + 132 * (int)sizeof(int) + MAXE * (int)sizeof(unsigned short);

    cudaFuncSetAttribute(k_fused, cudaFuncAttributeMaxDynamicSharedMemorySize, SMEM);

    k_csr<<<1, 256>>>(ei, E);
    k_fused<<<Bn, 256, SMEM>>>(x, embW, embB, WlA, blA, WrA, brA,
                               attA, gbA, gA, beA, pW, pB, out, nE);
}

// round 4
// speedup vs baseline: 1.9065x; 1.1859x over previous
#include <cuda_runtime.h>
#include <math.h>

#define Bn 256
#define Ln 256
#define Cn 128
#define HIDn 128
#define MAXE 4352        // 4096 edges + 128 self loops
#define NT 512           // threads per CTA (16 warps)

// ---------------- device scratch (no allocs allowed) ----------------
__device__ int g_ptr[Cn + 1];
__device__ unsigned short g_src[MAXE];

// ---------------- f32x2 packed-FMA helpers ----------------
__device__ __forceinline__ unsigned long long fma2(unsigned long long a,
                                                   unsigned long long b,
                                                   unsigned long long c) {
    unsigned long long d;
    asm("fma.rn.f32x2 %0, %1, %2, %3;" : "=l"(d) : "l"(a), "l"(b), "l"(c));
    return d;
}
__device__ __forceinline__ unsigned long long pack2(float x) {
    unsigned long long r;
    unsigned u = __float_as_uint(x);
    asm("mov.b64 %0, {%1, %1};" : "=l"(r) : "r"(u));
    return r;
}
__device__ __forceinline__ float lo2(unsigned long long v) {
    return __uint_as_float((unsigned)v);
}
__device__ __forceinline__ float hi2(unsigned long long v) {
    return __uint_as_float((unsigned)(v >> 32));
}

// ---------------- single-kernel CSR build ----------------
__global__ void k_csr(const void* ei, int E) {
    __shared__ int cnt[Cn];
    __shared__ int base[Cn + 1];
    __shared__ int is64s;
    int tid = threadIdx.x;

    if (tid < 32) {
        int v = ((const int*)ei)[tid * 2 + 1];
        unsigned ball = __ballot_sync(0xffffffffu, v != 0);
        if (tid == 0) is64s = (ball == 0) ? 1 : 0;
    }
    if (tid < Cn) cnt[tid] = 1;              // self loop
    __syncthreads();
    int is64 = is64s;

    for (int e = tid; e < E; e += blockDim.x) {
        int d = is64 ? (int)((const long long*)ei)[E + e] : ((const int*)ei)[E + e];
        atomicAdd(&cnt[d], 1);
    }
    __syncthreads();

    if (tid < 32) {  // warp scan: 4 counts per lane
        int c0 = cnt[tid*4], c1 = cnt[tid*4+1], c2 = cnt[tid*4+2], c3 = cnt[tid*4+3];
        int s = c0 + c1 + c2 + c3;
        int pre = s;
#pragma unroll
        for (int off = 1; off < 32; off <<= 1) {
            int t = __shfl_up_sync(0xffffffffu, pre, off);
            if (tid >= off) pre += t;
        }
        int excl = pre - s;
        base[tid*4]     = excl;
        base[tid*4 + 1] = excl + c0;
        base[tid*4 + 2] = excl + c0 + c1;
        base[tid*4 + 3] = excl + c0 + c1 + c2;
        if (tid == 31) base[Cn] = pre;
    }
    __syncthreads();
    if (tid <= Cn) g_ptr[tid] = base[tid];
    if (tid < Cn) cnt[tid] = base[tid];      // reuse as cursor
    __syncthreads();

    for (int e = tid; e < E; e += blockDim.x) {
        int s = is64 ? (int)((const long long*)ei)[e]     : ((const int*)ei)[e];
        int d = is64 ? (int)((const long long*)ei)[E + e] : ((const int*)ei)[E + e];
        int p = atomicAdd(&cnt[d], 1);
        g_src[p] = (unsigned short)s;
    }
    __syncthreads();
    if (tid < Cn) {                           // self loop entries
        int p = atomicAdd(&cnt[tid], 1);
        g_src[p] = (unsigned short)tid;
    }
}

// ---------------- GEMM: Osm[128x128] = Asm[128x128] @ Wg[128x128] + bias ----------------
// 512 threads; warp owns 8 rows (c0 = warp*8); lane owns 4 cols (j0 = lane*4).
// a-loads: warp-uniform broadcast float4 (4 k at a time); b: one LDS.128 row slice.
__device__ __forceinline__ void gemm128(const float* __restrict__ Asm,
                                        const float* __restrict__ Wg,
                                        const float* __restrict__ bias,
                                        float* __restrict__ Osm,
                                        float* __restrict__ stage,
                                        int tid) {
    int warp = tid >> 5, lane = tid & 31;
    int c0 = warp * 8, j0 = lane * 4;
    unsigned long long acc[8][2];
#pragma unroll
    for (int i = 0; i < 8; i++) { acc[i][0] = 0ull; acc[i][1] = 0ull; }

    for (int k0 = 0; k0 < 128; k0 += 32) {
        __syncthreads();
        for (int i = tid; i < 1024; i += NT)
            ((float4*)stage)[i] = ((const float4*)(Wg + k0 * 128))[i];
        __syncthreads();
#pragma unroll
        for (int kk4 = 0; kk4 < 32; kk4 += 4) {
            float4 a4[8];
#pragma unroll
            for (int i = 0; i < 8; i++)
                a4[i] = *(const float4*)(Asm + (c0 + i) * 128 + k0 + kk4);
#pragma unroll
            for (int kk = 0; kk < 4; kk++) {
                ulonglong2 bq = *(const ulonglong2*)(stage + (kk4 + kk) * 128 + j0);
#pragma unroll
                for (int i = 0; i < 8; i++) {
                    float av = ((const float*)&a4[i])[kk];
                    unsigned long long a2 = pack2(av);
                    acc[i][0] = fma2(a2, bq.x, acc[i][0]);
                    acc[i][1] = fma2(a2, bq.y, acc[i][1]);
                }
            }
        }
    }
    float4 b4 = *(const float4*)(bias + j0);
#pragma unroll
    for (int i = 0; i < 8; i++) {
        float4 v = {lo2(acc[i][0]) + b4.x, hi2(acc[i][0]) + b4.y,
                    lo2(acc[i][1]) + b4.z, hi2(acc[i][1]) + b4.w};
        *(float4*)(Osm + (c0 + i) * 128 + j0) = v;
    }
}

// ---------------- GAT layer (GEMMs + single-pass softmax agg + ELU + residual + LN) ----------------
// ATT: per-warp 128-float rowbuf; after inv known, a recompute mini-pass
// accumulates normalized head-mean alpha (handles duplicate edges), then one
// float4 store per lane to global.
template <bool ATT>
__device__ __forceinline__ void gat_layer(
    float* hs, float* xls, float* xrs, float* stage, float* rowbuf,
    const int* sptr, const unsigned short* ssrc,
    const float* __restrict__ Wl, const float* __restrict__ bl,
    const float* __restrict__ Wr, const float* __restrict__ br,
    const float* __restrict__ att, const float* __restrict__ gbias,
    const float* __restrict__ gamma, const float* __restrict__ beta,
    float* attn_rows, int tid) {

    gemm128(hs, Wl, bl, xls, stage, tid);
    gemm128(hs, Wr, br, xrs, stage, tid);
    __syncthreads();

    int warp = tid >> 5, lane = tid & 31;
    int hh = lane >> 3;
    int k4 = lane * 4;
    float4 a4 = *(const float4*)(att + hh * 32 + (lane & 7) * 4);
    float* rb = rowbuf + warp * 128;

    for (int c = warp; c < Cn; c += 16) {
        int e0 = sptr[c], e1 = sptr[c + 1];
        float4 xr4 = *(const float4*)(xrs + c * 128 + k4);
        float sp = 0.f;
        float4 acc = make_float4(0.f, 0.f, 0.f, 0.f);
        // single pass: no max-shift needed — logits are O(1) by construction
#pragma unroll 2
        for (int e = e0; e < e1; e++) {
            int s = ssrc[e];
            float4 x4 = *(const float4*)(xls + s * 128 + k4);
            float t0 = x4.x + xr4.x; t0 = t0 > 0.f ? t0 : 0.2f * t0;
            float t1 = x4.y + xr4.y; t1 = t1 > 0.f ? t1 : 0.2f * t1;
            float t2 = x4.z + xr4.z; t2 = t2 > 0.f ? t2 : 0.2f * t2;
            float t3 = x4.w + xr4.w; t3 = t3 > 0.f ? t3 : 0.2f * t3;
            float v = t0 * a4.x + t1 * a4.y + t2 * a4.z + t3 * a4.w;
            v += __shfl_xor_sync(0xffffffffu, v, 1);
            v += __shfl_xor_sync(0xffffffffu, v, 2);
            v += __shfl_xor_sync(0xffffffffu, v, 4);
            float p = __expf(v);
            sp += p;
            acc.x += p * x4.x; acc.y += p * x4.y; acc.z += p * x4.z; acc.w += p * x4.w;
        }
        float inv = 1.0f / (sp + 1e-16f);

        // epilogue: +gat_bias, ELU, residual, LayerNorm (in-place into hs)
        float4 gb4 = *(const float4*)(gbias + k4);
        float4 h4 = *(const float4*)(hs + c * 128 + k4);
        float val[4];
        {
            float o;
            o = acc.x * inv + gb4.x; o = o > 0.f ? o : expm1f(o); val[0] = h4.x + o;
            o = acc.y * inv + gb4.y; o = o > 0.f ? o : expm1f(o); val[1] = h4.y + o;
            o = acc.z * inv + gb4.z; o = o > 0.f ? o : expm1f(o); val[2] = h4.z + o;
            o = acc.w * inv + gb4.w; o = o > 0.f ? o : expm1f(o); val[3] = h4.w + o;
        }
        float s1 = val[0] + val[1] + val[2] + val[3];
#pragma unroll
        for (int off = 16; off; off >>= 1) s1 += __shfl_xor_sync(0xffffffffu, s1, off);
        float mu = s1 * (1.0f / 128.0f);
        float d0 = val[0] - mu, d1 = val[1] - mu, d2 = val[2] - mu, d3 = val[3] - mu;
        float s2 = d0 * d0 + d1 * d1 + d2 * d2 + d3 * d3;
#pragma unroll
        for (int off = 16; off; off >>= 1) s2 += __shfl_xor_sync(0xffffffffu, s2, off);
        float rs = rsqrtf(s2 * (1.0f / 128.0f) + 1e-5f);
        float4 g4 = *(const float4*)(gamma + k4);
        float4 be4 = *(const float4*)(beta + k4);
        float4 outv;
        outv.x = d0 * rs * g4.x + be4.x;
        outv.y = d1 * rs * g4.y + be4.y;
        outv.z = d2 * rs * g4.z + be4.z;
        outv.w = d3 * rs * g4.w + be4.w;
        *(float4*)(hs + c * 128 + k4) = outv;

        if (ATT) {
            // zero 128-float row (one float4 per lane)
            *(float4*)(rb + k4) = make_float4(0.f, 0.f, 0.f, 0.f);
            __syncwarp();
            // recompute mini-pass: normalized head-mean alpha per edge
            for (int e = e0; e < e1; e++) {
                int s = ssrc[e];
                float4 x4 = *(const float4*)(xls + s * 128 + k4);
                float t0 = x4.x + xr4.x; t0 = t0 > 0.f ? t0 : 0.2f * t0;
                float t1 = x4.y + xr4.y; t1 = t1 > 0.f ? t1 : 0.2f * t1;
                float t2 = x4.z + xr4.z; t2 = t2 > 0.f ? t2 : 0.2f * t2;
                float t3 = x4.w + xr4.w; t3 = t3 > 0.f ? t3 : 0.2f * t3;
                float v = t0 * a4.x + t1 * a4.y + t2 * a4.z + t3 * a4.w;
                v += __shfl_xor_sync(0xffffffffu, v, 1);
                v += __shfl_xor_sync(0xffffffffu, v, 2);
                v += __shfl_xor_sync(0xffffffffu, v, 4);
                float am = __expf(v) * inv;     // this lane's head alpha
                am += __shfl_xor_sync(0xffffffffu, am, 8);
                am += __shfl_xor_sync(0xffffffffu, am, 16);
                if (lane == 0) rb[s] += am * 0.25f;
            }
            __syncwarp();
            *(float4*)(attn_rows + (size_t)c * 128 + k4) = *(const float4*)(rb + k4);
        }
    }
    __syncthreads();
}

// ---------------- fully fused: embed -> layer0 -> layer1(+attn) -> proj ----------------
__global__ void __launch_bounds__(NT) k_fused(
    const float* __restrict__ x,
    const float* __restrict__ embW, const float* __restrict__ embB,
    const float* __restrict__ WlA, const float* __restrict__ blA,
    const float* __restrict__ WrA, const float* __restrict__ brA,
    const float* __restrict__ attA, const float* __restrict__ gbA,
    const float* __restrict__ gA, const float* __restrict__ beA,
    const float* __restrict__ pW, const float* __restrict__ pB,
    float* __restrict__ out, int nE) {

    extern __shared__ float smem[];
    float* hs = smem;                    // 128*128
    float* xls = hs + 16384;
    float* xrs = xls + 16384;
    float* stage = xrs + 16384;          // 4096 floats (32x128)
    float* rowbuf = stage + 4096;        // 16 warps x 128
    int* sptr = (int*)(rowbuf + 2048);   // 132 ints
    unsigned short* ssrc = (unsigned short*)(sptr + 132);

    int b = blockIdx.x, tid = threadIdx.x;
    int warp = tid >> 5, lane = tid & 31;
    int c0 = warp * 8, j0 = lane * 4;

    for (int i = tid; i <= Cn; i += NT) sptr[i] = g_ptr[i];
    for (int i = tid; i < nE; i += NT) ssrc[i] = g_src[i];

    // ---- embed: hs[c][j] = sum_l x[b,l,c] * embW[l,j] + embB[j], K = 256
    {
        unsigned long long acc[8][2];
#pragma unroll
        for (int i = 0; i < 8; i++) { acc[i][0] = 0ull; acc[i][1] = 0ull; }
        const float* xb = x + (size_t)b * Ln * Cn;
        float* xs = stage;           // 16x128
        float* wstage = stage + 2048;
        for (int l0 = 0; l0 < Ln; l0 += 16) {
            __syncthreads();
            for (int i = tid; i < 512; i += NT) {
                ((float4*)xs)[i] = ((const float4*)(xb + (size_t)l0 * Cn))[i];
                ((float4*)wstage)[i] = ((const float4*)(embW + (size_t)l0 * HIDn))[i];
            }
            __syncthreads();
#pragma unroll
            for (int l = 0; l < 16; l++) {
                float4 alo = *(const float4*)(xs + l * 128 + c0);      // rows c0..c0+3
                float4 ahi = *(const float4*)(xs + l * 128 + c0 + 4);  // rows c0+4..c0+7
                ulonglong2 bq = *(const ulonglong2*)(wstage + l * 128 + j0);
                float av[8] = {alo.x, alo.y, alo.z, alo.w, ahi.x, ahi.y, ahi.z, ahi.w};
#pragma unroll
                for (int i = 0; i < 8; i++) {
                    unsigned long long a2 = pack2(av[i]);
                    acc[i][0] = fma2(a2, bq.x, acc[i][0]);
                    acc[i][1] = fma2(a2, bq.y, acc[i][1]);
                }
            }
        }
        float4 eb4 = *(const float4*)(embB + j0);
#pragma unroll
        for (int i = 0; i < 8; i++) {
            float4 v = {lo2(acc[i][0]) + eb4.x, hi2(acc[i][0]) + eb4.y,
                        lo2(acc[i][1]) + eb4.z, hi2(acc[i][1]) + eb4.w};
            *(float4*)(hs + (c0 + i) * 128 + j0) = v;
        }
    }
    // (gemm128's leading __syncthreads orders hs writes before reads)

    float* attn = out + (size_t)Bn * Ln * Cn + (size_t)b * Cn * Cn;
    gat_layer<false>(hs, xls, xrs, stage, rowbuf, sptr, ssrc,
                     WlA, blA, WrA, brA, attA, gbA, gA, beA, nullptr, tid);
    gat_layer<true>(hs, xls, xrs, stage, rowbuf, sptr, ssrc,
                    WlA + HIDn * HIDn, blA + HIDn, WrA + HIDn * HIDn, brA + HIDn,
                    attA + 128, gbA + HIDn, gA + HIDn, beA + HIDn, attn, tid);

    // ---- proj: out[b,l,c] = sum_j hs[c][j] * pW[j][l] + pB[l]
    for (int lh = 0; lh < 2; lh++) {
        unsigned long long acc[8][2];
#pragma unroll
        for (int i = 0; i < 8; i++) { acc[i][0] = 0ull; acc[i][1] = 0ull; }
        for (int k0 = 0; k0 < 128; k0 += 32) {
            __syncthreads();
            for (int i = tid; i < 1024; i += NT) {
                int kk = i >> 5, c4 = i & 31;
                *(float4*)(stage + kk * 128 + c4 * 4) =
                    *(const float4*)(pW + (size_t)(k0 + kk) * Ln + lh * 128 + c4 * 4);
            }
            __syncthreads();
#pragma unroll
            for (int kk4 = 0; kk4 < 32; kk4 += 4) {
                float4 a4[8];
#pragma unroll
                for (int i = 0; i < 8; i++)
                    a4[i] = *(const float4*)(hs + (c0 + i) * 128 + k0 + kk4);
#pragma unroll
                for (int kk = 0; kk < 4; kk++) {
                    ulonglong2 bq = *(const ulonglong2*)(stage + (kk4 + kk) * 128 + j0);
#pragma unroll
                    for (int i = 0; i < 8; i++) {
                        float av = ((const float*)&a4[i])[kk];
                        unsigned long long a2 = pack2(av);
                        acc[i][0] = fma2(a2, bq.x, acc[i][0]);
                        acc[i][1] = fma2(a2, bq.y, acc[i][1]);
                    }
                }
            }
        }
        // acc[i][t]: row c0+i, cols (j0+2t, j0+2t+1) of this 128-l half
        float4 pb4 = *(const float4*)(pB + lh * 128 + j0);
        float colv[4][8];
#pragma unroll
        for (int i = 0; i < 8; i++) {
            colv[0][i] = lo2(acc[i][0]) + pb4.x;
            colv[1][i] = hi2(acc[i][0]) + pb4.y;
            colv[2][i] = lo2(acc[i][1]) + pb4.z;
            colv[3][i] = hi2(acc[i][1]) + pb4.w;
        }
#pragma unroll
        for (int jj = 0; jj < 4; jj++) {
            int l = lh * 128 + j0 + jj;
            float* dst = out + (size_t)b * Ln * Cn + (size_t)l * Cn + c0;
            float4 v0 = {colv[jj][0], colv[jj][1], colv[jj][2], colv[jj][3]};
            float4 v1 = {colv[jj][4], colv[jj][5], colv[jj][6], colv[jj][7]};
            *(float4*)dst = v0;
            *(float4*)(dst + 4) = v1;
        }
    }
}

// ---------------- launch ----------------
extern "C" void kernel_launch(void* const* d_in, const int* in_sizes, int n_in,
                              void* d_out, int out_size) {
    const float* x    = (const float*)d_in[0];
    const void*  ei   = d_in[1];
    const float* embW = (const float*)d_in[2];
    const float* embB = (const float*)d_in[3];
    const float* WlA  = (const float*)d_in[4];
    const float* blA  = (const float*)d_in[5];
    const float* WrA  = (const float*)d_in[6];
    const float* brA  = (const float*)d_in[7];
    const float* attA = (const float*)d_in[8];
    const float* gbA  = (const float*)d_in[9];
    const float* gA   = (const float*)d_in[10];
    const float* beA  = (const float*)d_in[11];
    const float* pW   = (const float*)d_in[12];
    const float* pB   = (const float*)d_in[13];
    float* out = (float*)d_out;

    int E = in_sizes[1] / 2;
    int nE = E + Cn;
    if (nE > MAXE) nE = MAXE;

    const int SMEM = (3 * 16384 + 4096 + 2048) * (int)sizeof(float)
                   + 132 * (int)sizeof(int) + MAXE * (int)sizeof(unsigned short);

    cudaFuncSetAttribute(k_fused, cudaFuncAttributeMaxDynamicSharedMemorySize, SMEM);

    k_csr<<<1, 256>>>(ei, E);
    k_fused<<<Bn, NT, SMEM>>>(x, embW, embB, WlA, blA, WrA, brA,
                              attA, gbA, gA, beA, pW, pB, out, nE);
}

// round 6
// speedup vs baseline: 2.3077x; 1.2104x over previous
#include <cuda_runtime.h>
#include <cuda_bf16.h>
#include <math.h>

#define Bn 256
#define Ln 256
#define Cn 128
#define HIDn 128
#define MAXE 4352
#define NT 512           // 16 warps
#define HS 132           // fp32 smem row stride
#define TS 136           // bf16 tile row stride (conflict-free fragment LDS)
#define TILE_HALF (128*TS)   // 17408 elements per (hi|lo) tile

// ---------------- device scratch ----------------
__device__ int g_ptr[Cn + 1];
__device__ unsigned short g_src[MAXE];

// ---------------- mma.sync bf16 (base ISA, no 'a' feature needed) ----------------
__device__ __forceinline__ void mma_bf16(float* c, const unsigned* a, const unsigned* b) {
    asm volatile("mma.sync.aligned.m16n8k16.row.col.f32.bf16.bf16.f32 "
        "{%0,%1,%2,%3}, {%4,%5,%6,%7}, {%8,%9}, {%0,%1,%2,%3};"
        : "+f"(c[0]), "+f"(c[1]), "+f"(c[2]), "+f"(c[3])
        : "r"(a[0]), "r"(a[1]), "r"(a[2]), "r"(a[3]), "r"(b[0]), "r"(b[1]));
}

// split fp32 -> (bf16 hi, bf16 lo) into tile
__device__ __forceinline__ void cvt_store(__nv_bfloat16* t, int row, int k, float v) {
    __nv_bfloat16 h = __float2bfloat16(v);
    t[row * TS + k] = h;
    t[TILE_HALF + row * TS + k] = __float2bfloat16(v - __bfloat162float(h));
}

// per-warp 32x32 GEMM over K=128: acc += A(128x128) @ B^T rows n (3-term bf16 split)
__device__ __forceinline__ void warp_gemm(const __nv_bfloat16* tA, const __nv_bfloat16* tB,
                                          float acc[2][4][4], int m0, int n0,
                                          int l4, int kq) {
#pragma unroll 2
    for (int ks = 0; ks < 8; ks++) {
        int k0 = ks * 16 + kq;
        unsigned ah[2][4], al[2][4], bh[4][2], bl[4][2];
#pragma unroll
        for (int mb = 0; mb < 2; mb++) {
            const __nv_bfloat16* p = tA + (m0 + mb * 16 + l4) * TS + k0;
            ah[mb][0] = *(const unsigned*)(p);
            ah[mb][1] = *(const unsigned*)(p + 8 * TS);
            ah[mb][2] = *(const unsigned*)(p + 8);
            ah[mb][3] = *(const unsigned*)(p + 8 * TS + 8);
            al[mb][0] = *(const unsigned*)(p + TILE_HALF);
            al[mb][1] = *(const unsigned*)(p + TILE_HALF + 8 * TS);
            al[mb][2] = *(const unsigned*)(p + TILE_HALF + 8);
            al[mb][3] = *(const unsigned*)(p + TILE_HALF + 8 * TS + 8);
        }
#pragma unroll
        for (int nb = 0; nb < 4; nb++) {
            const __nv_bfloat16* p = tB + (n0 + nb * 8 + l4) * TS + k0;
            bh[nb][0] = *(const unsigned*)(p);
            bh[nb][1] = *(const unsigned*)(p + 8);
            bl[nb][0] = *(const unsigned*)(p + TILE_HALF);
            bl[nb][1] = *(const unsigned*)(p + TILE_HALF + 8);
        }
#pragma unroll
        for (int mb = 0; mb < 2; mb++)
#pragma unroll
            for (int nb = 0; nb < 4; nb++) {
                mma_bf16(acc[mb][nb], ah[mb], bh[nb]);
                mma_bf16(acc[mb][nb], ah[mb], bl[nb]);
                mma_bf16(acc[mb][nb], al[mb], bh[nb]);
            }
    }
}

// ---------------- single-kernel CSR build ----------------
__global__ void k_csr(const void* ei, int E) {
    __shared__ int cnt[Cn];
    __shared__ int base[Cn + 1];
    __shared__ int is64s;
    int tid = threadIdx.x;
    if (tid < 32) {
        int v = ((const int*)ei)[tid * 2 + 1];
        unsigned ball = __ballot_sync(0xffffffffu, v != 0);
        if (tid == 0) is64s = (ball == 0) ? 1 : 0;
    }
    if (tid < Cn) cnt[tid] = 1;
    __syncthreads();
    int is64 = is64s;
    for (int e = tid; e < E; e += blockDim.x) {
        int d = is64 ? (int)((const long long*)ei)[E + e] : ((const int*)ei)[E + e];
        atomicAdd(&cnt[d], 1);
    }
    __syncthreads();
    if (tid < 32) {
        int c0 = cnt[tid*4], c1 = cnt[tid*4+1], c2 = cnt[tid*4+2], c3 = cnt[tid*4+3];
        int s = c0 + c1 + c2 + c3;
        int pre = s;
#pragma unroll
        for (int off = 1; off < 32; off <<= 1) {
            int t = __shfl_up_sync(0xffffffffu, pre, off);
            if (tid >= off) pre += t;
        }
        int excl = pre - s;
        base[tid*4] = excl; base[tid*4+1] = excl + c0;
        base[tid*4+2] = excl + c0 + c1; base[tid*4+3] = excl + c0 + c1 + c2;
        if (tid == 31) base[Cn] = pre;
    }
    __syncthreads();
    if (tid <= Cn) g_ptr[tid] = base[tid];
    if (tid < Cn) cnt[tid] = base[tid];
    __syncthreads();
    for (int e = tid; e < E; e += blockDim.x) {
        int s = is64 ? (int)((const long long*)ei)[e]     : ((const int*)ei)[e];
        int d = is64 ? (int)((const long long*)ei)[E + e] : ((const int*)ei)[E + e];
        int p = atomicAdd(&cnt[d], 1);
        g_src[p] = (unsigned short)s;
    }
    __syncthreads();
    if (tid < Cn) {
        int p = atomicAdd(&cnt[tid], 1);
        g_src[p] = (unsigned short)tid;
    }
}

// ---------------- GAT layer ----------------
template <bool ATT>
__device__ __forceinline__ void gat_layer(
    float* hs, float* xls, float* xrs,
    __nv_bfloat16* tA, __nv_bfloat16* tB, float* rowbuf,
    const int* sptr, const unsigned short* ssrc,
    const float* __restrict__ Wl, const float* __restrict__ bl,
    const float* __restrict__ Wr, const float* __restrict__ br,
    const float* __restrict__ att, const float* __restrict__ gbias,
    const float* __restrict__ gamma, const float* __restrict__ beta,
    float* attn_rows, int tid) {

    int warp = tid >> 5, lane = tid & 31;
    int l4 = lane >> 2, kq = 2 * (lane & 3);
    int m0 = (warp & 3) * 32, n0 = (warp >> 2) * 32;

    // tiles: A <- hs [c][j], B <- Wl^T ([j_out][j_in])
    for (int idx = tid; idx < 16384; idx += NT) {
        int r = idx >> 7, k = idx & 127;
        cvt_store(tA, r, k, hs[r * HS + k]);
        cvt_store(tB, k, r, Wl[idx]);        // Wl[r=k_in][k=j_out] -> B[j_out][k_in]
    }
    __syncthreads();

    float accL[2][4][4], accR[2][4][4];
#pragma unroll
    for (int mb = 0; mb < 2; mb++)
#pragma unroll
        for (int nb = 0; nb < 4; nb++)
#pragma unroll
            for (int i = 0; i < 4; i++) { accL[mb][nb][i] = 0.f; accR[mb][nb][i] = 0.f; }

    warp_gemm(tA, tB, accL, m0, n0, l4, kq);
    __syncthreads();
    for (int idx = tid; idx < 16384; idx += NT)
        cvt_store(tB, idx & 127, idx >> 7, Wr[idx]);
    __syncthreads();
    warp_gemm(tA, tB, accR, m0, n0, l4, kq);
    __syncthreads();   // tiles consumed -> xls/xrs may overwrite

#pragma unroll
    for (int mb = 0; mb < 2; mb++)
#pragma unroll
        for (int nb = 0; nb < 4; nb++) {
            int row = m0 + mb * 16 + l4;
            int col = n0 + nb * 8 + kq;
            float2 bl2 = *(const float2*)(bl + col);
            float2 br2 = *(const float2*)(br + col);
            float2 v;
            v.x = accL[mb][nb][0] + bl2.x; v.y = accL[mb][nb][1] + bl2.y;
            *(float2*)(xls + row * HS + col) = v;
            v.x = accL[mb][nb][2] + bl2.x; v.y = accL[mb][nb][3] + bl2.y;
            *(float2*)(xls + (row + 8) * HS + col) = v;
            v.x = accR[mb][nb][0] + br2.x; v.y = accR[mb][nb][1] + br2.y;
            *(float2*)(xrs + row * HS + col) = v;
            v.x = accR[mb][nb][2] + br2.x; v.y = accR[mb][nb][3] + br2.y;
            *(float2*)(xrs + (row + 8) * HS + col) = v;
        }
    __syncthreads();

    // ---- edge softmax aggregation (fp32) ----
    int hh = lane >> 3;
    int k4 = lane * 4;
    float4 a4 = *(const float4*)(att + hh * 32 + (lane & 7) * 4);
    float* rb = rowbuf + warp * 128;

    for (int c = warp; c < Cn; c += 16) {
        int e0 = sptr[c], e1 = sptr[c + 1];
        float4 xr4 = *(const float4*)(xrs + c * HS + k4);
        float sp = 0.f;
        float4 acc = make_float4(0.f, 0.f, 0.f, 0.f);
#pragma unroll 2
        for (int e = e0; e < e1; e++) {
            int s = ssrc[e];
            float4 x4 = *(const float4*)(xls + s * HS + k4);
            float t0 = x4.x + xr4.x; t0 = t0 > 0.f ? t0 : 0.2f * t0;
            float t1 = x4.y + xr4.y; t1 = t1 > 0.f ? t1 : 0.2f * t1;
            float t2 = x4.z + xr4.z; t2 = t2 > 0.f ? t2 : 0.2f * t2;
            float t3 = x4.w + xr4.w; t3 = t3 > 0.f ? t3 : 0.2f * t3;
            float v = t0 * a4.x + t1 * a4.y + t2 * a4.z + t3 * a4.w;
            v += __shfl_xor_sync(0xffffffffu, v, 1);
            v += __shfl_xor_sync(0xffffffffu, v, 2);
            v += __shfl_xor_sync(0xffffffffu, v, 4);
            float p = __expf(v);
            sp += p;
            acc.x += p * x4.x; acc.y += p * x4.y; acc.z += p * x4.z; acc.w += p * x4.w;
        }
        float inv = 1.0f / (sp + 1e-16f);

        float4 gb4 = *(const float4*)(gbias + k4);
        float4 h4 = *(const float4*)(hs + c * HS + k4);
        float val[4];
        {
            float o;
            o = acc.x * inv + gb4.x; o = o > 0.f ? o : expm1f(o); val[0] = h4.x + o;
            o = acc.y * inv + gb4.y; o = o > 0.f ? o : expm1f(o); val[1] = h4.y + o;
            o = acc.z * inv + gb4.z; o = o > 0.f ? o : expm1f(o); val[2] = h4.z + o;
            o = acc.w * inv + gb4.w; o = o > 0.f ? o : expm1f(o); val[3] = h4.w + o;
        }
        float s1 = val[0] + val[1] + val[2] + val[3];
#pragma unroll
        for (int off = 16; off; off >>= 1) s1 += __shfl_xor_sync(0xffffffffu, s1, off);
        float mu = s1 * (1.0f / 128.0f);
        float d0 = val[0] - mu, d1 = val[1] - mu, d2 = val[2] - mu, d3 = val[3] - mu;
        float s2 = d0 * d0 + d1 * d1 + d2 * d2 + d3 * d3;
#pragma unroll
        for (int off = 16; off; off >>= 1) s2 += __shfl_xor_sync(0xffffffffu, s2, off);
        float rs = rsqrtf(s2 * (1.0f / 128.0f) + 1e-5f);
        float4 g4 = *(const float4*)(gamma + k4);
        float4 be4 = *(const float4*)(beta + k4);
        float4 outv;
        outv.x = d0 * rs * g4.x + be4.x;
        outv.y = d1 * rs * g4.y + be4.y;
        outv.z = d2 * rs * g4.z + be4.z;
        outv.w = d3 * rs * g4.w + be4.w;
        *(float4*)(hs + c * HS + k4) = outv;

        if (ATT) {
            *(float4*)(rb + k4) = make_float4(0.f, 0.f, 0.f, 0.f);
            __syncwarp();
            for (int e = e0; e < e1; e++) {
                int s = ssrc[e];
                float4 x4 = *(const float4*)(xls + s * HS + k4);
                float t0 = x4.x + xr4.x; t0 = t0 > 0.f ? t0 : 0.2f * t0;
                float t1 = x4.y + xr4.y; t1 = t1 > 0.f ? t1 : 0.2f * t1;
                float t2 = x4.z + xr4.z; t2 = t2 > 0.f ? t2 : 0.2f * t2;
                float t3 = x4.w + xr4.w; t3 = t3 > 0.f ? t3 : 0.2f * t3;
                float v = t0 * a4.x + t1 * a4.y + t2 * a4.z + t3 * a4.w;
                v += __shfl_xor_sync(0xffffffffu, v, 1);
                v += __shfl_xor_sync(0xffffffffu, v, 2);
                v += __shfl_xor_sync(0xffffffffu, v, 4);
                float am = __expf(v) * inv;
                am += __shfl_xor_sync(0xffffffffu, am, 8);
                am += __shfl_xor_sync(0xffffffffu, am, 16);
                if (lane == 0) rb[s] += am * 0.25f;
            }
            __syncwarp();
            *(float4*)(attn_rows + (size_t)c * 128 + k4) = *(const float4*)(rb + k4);
        }
    }
    __syncthreads();
}

// ---------------- fully fused kernel ----------------
__global__ void __launch_bounds__(NT, 1) k_fused(
    const float* __restrict__ x,
    const float* __restrict__ embW, const float* __restrict__ embB,
    const float* __restrict__ WlA, const float* __restrict__ blA,
    const float* __restrict__ WrA, const float* __restrict__ brA,
    const float* __restrict__ attA, const float* __restrict__ gbA,
    const float* __restrict__ gA, const float* __restrict__ beA,
    const float* __restrict__ pW, const float* __restrict__ pB,
    float* __restrict__ out, int nE) {

    extern __shared__ char sm[];
    float* hs = (float*)sm;                                  // 128x132 fp32 = 67584 B
    char* tiles = sm + 67584;                                // 139264 B
    __nv_bfloat16* tA = (__nv_bfloat16*)tiles;               // hi+lo = 69632 B
    __nv_bfloat16* tB = (__nv_bfloat16*)(tiles + 69632);
    float* xls = (float*)tiles;                              // alias (67584 B)
    float* xrs = (float*)(tiles + 67584);
    float* rowbuf = (float*)(sm + 206848);                   // 8192 B
    int* sptr = (int*)(sm + 215040);                         // 528 B
    unsigned short* ssrc = (unsigned short*)(sm + 215568);   // 8704 B

    int b = blockIdx.x, tid = threadIdx.x;
    int warp = tid >> 5, lane = tid & 31;
    int l4 = lane >> 2, kq = 2 * (lane & 3);
    int m0 = (warp & 3) * 32, n0 = (warp >> 2) * 32;

    for (int i = tid; i <= Cn; i += NT) sptr[i] = g_ptr[i];
    for (int i = tid; i < nE; i += NT) ssrc[i] = g_src[i];

    // ---- embed: hs[c][j] = sum_l x[b][l][c] * embW[l][j] + embB[j]
    {
        float accE[2][4][4];
#pragma unroll
        for (int mb = 0; mb < 2; mb++)
#pragma unroll
            for (int nb = 0; nb < 4; nb++)
#pragma unroll
                for (int i = 0; i < 4; i++) accE[mb][nb][i] = 0.f;

        const float* xb = x + (size_t)b * Ln * Cn;
        for (int chunk = 0; chunk < 2; chunk++) {
            int l0c = chunk * 128;
            for (int idx = tid; idx < 16384; idx += NT) {
                int u = idx >> 7, c = idx & 127;
                cvt_store(tA, c, u, xb[(size_t)(l0c + u) * Cn + c]);      // A[c][l]
                cvt_store(tB, c, u, embW[(size_t)(l0c + u) * HIDn + c]);  // B[j][l]
            }
            __syncthreads();
            warp_gemm(tA, tB, accE, m0, n0, l4, kq);
            __syncthreads();
        }
#pragma unroll
        for (int mb = 0; mb < 2; mb++)
#pragma unroll
            for (int nb = 0; nb < 4; nb++) {
                int row = m0 + mb * 16 + l4;
                int col = n0 + nb * 8 + kq;
                float2 eb2 = *(const float2*)(embB + col);
                float2 v;
                v.x = accE[mb][nb][0] + eb2.x; v.y = accE[mb][nb][1] + eb2.y;
                *(float2*)(hs + row * HS + col) = v;
                v.x = accE[mb][nb][2] + eb2.x; v.y = accE[mb][nb][3] + eb2.y;
                *(float2*)(hs + (row + 8) * HS + col) = v;
            }
        __syncthreads();
    }

    float* attn = out + (size_t)Bn * Ln * Cn + (size_t)b * Cn * Cn;
    gat_layer<false>(hs, xls, xrs, tA, tB, rowbuf, sptr, ssrc,
                     WlA, blA, WrA, brA, attA, gbA, gA, beA, nullptr, tid);
    gat_layer<true>(hs, xls, xrs, tA, tB, rowbuf, sptr, ssrc,
                    WlA + HIDn * HIDn, blA + HIDn, WrA + HIDn * HIDn, brA + HIDn,
                    attA + 128, gbA + HIDn, gA + HIDn, beA + HIDn, attn, tid);

    // ---- proj: out[b][l][c] = sum_j hs[c][j] * pW[j][l] + pB[l]
    // A[m=l'][k=j] = pW[j][lbase+l'] ; B[n=c][k=j] = hs[c][j]
    for (int idx = tid; idx < 16384; idx += NT) {
        int r = idx >> 7, k = idx & 127;
        cvt_store(tB, r, k, hs[r * HS + k]);
    }
    float* outb = out + (size_t)b * Ln * Cn;
    for (int half = 0; half < 2; half++) {
        for (int idx = tid; idx < 16384; idx += NT) {
            int j = idx >> 7, u = idx & 127;
            cvt_store(tA, u, j, pW[(size_t)j * Ln + half * 128 + u]);
        }
        __syncthreads();
        float accP[2][4][4];
#pragma unroll
        for (int mb = 0; mb < 2; mb++)
#pragma unroll
            for (int nb = 0; nb < 4; nb++)
#pragma unroll
                for (int i = 0; i < 4; i++) accP[mb][nb][i] = 0.f;
        warp_gemm(tA, tB, accP, m0, n0, l4, kq);
#pragma unroll
        for (int mb = 0; mb < 2; mb++)
#pragma unroll
            for (int nb = 0; nb < 4; nb++) {
                int l = half * 128 + m0 + mb * 16 + l4;
                int c = n0 + nb * 8 + kq;
                float pb0 = pB[l], pb1 = pB[l + 8];
                float2 v;
                v.x = accP[mb][nb][0] + pb0; v.y = accP[mb][nb][1] + pb0;
                *(float2*)(outb + (size_t)l * Cn + c) = v;
                v.x = accP[mb][nb][2] + pb1; v.y = accP[mb][nb][3] + pb1;
                *(float2*)(outb + (size_t)(l + 8) * Cn + c) = v;
            }
        __syncthreads();   // before tA overwrite for half 1
    }
}

// ---------------- launch ----------------
extern "C" void kernel_launch(void* const* d_in, const int* in_sizes, int n_in,
                              void* d_out, int out_size) {
    const float* x    = (const float*)d_in[0];
    const void*  ei   = d_in[1];
    const float* embW = (const float*)d_in[2];
    const float* embB = (const float*)d_in[3];
    const float* WlA  = (const float*)d_in[4];
    const float* blA  = (const float*)d_in[5];
    const float* WrA  = (const float*)d_in[6];
    const float* brA  = (const float*)d_in[7];
    const float* attA = (const float*)d_in[8];
    const float* gbA  = (const float*)d_in[9];
    const float* gA   = (const float*)d_in[10];
    const float* beA  = (const float*)d_in[11];
    const float* pW   = (const float*)d_in[12];
    const float* pB   = (const float*)d_in[13];
    float* out = (float*)d_out;

    int E = in_sizes[1] / 2;
    int nE = E + Cn;
    if (nE > MAXE) nE = MAXE;

    const int SMEM = 224272;

    cudaFuncSetAttribute(k_fused, cudaFuncAttributeMaxDynamicSharedMemorySize, SMEM);

    k_csr<<<1, 256>>>(ei, E);
    k_fused<<<Bn, NT, SMEM>>>(x, embW, embB, WlA, blA, WrA, brA,
                              attA, gbA, gA, beA, pW, pB, out, nE);
}

// round 7
// speedup vs baseline: 2.3747x; 1.0291x over previous
#include <cuda_runtime.h>
#include <cuda_bf16.h>
#include <math.h>

#define Bn 256
#define Ln 256
#define Cn 128
#define HIDn 128
#define MAXE 4352
#define NT 512           // 16 warps
#define HS 132           // fp32 smem row stride
#define TS 136           // bf16 tile row stride (conflict-free fragment LDS)
#define TILE_HALF (128*TS)   // 17408 bf16 per (hi|lo) half

// ---------------- device scratch ----------------
__device__ int g_ptr[Cn + 1];
__device__ unsigned short g_src[MAXE];
// precomputed weight split-tiles: [0,1]=embW chunks, [2..5]=Wl0,Wr0,Wl1,Wr1, [6,7]=pW halves
__device__ __nv_bfloat16 g_wt[8][2 * TILE_HALF];

// ---------------- mma.sync bf16 (base ISA) ----------------
__device__ __forceinline__ void mma_bf16(float* c, const unsigned* a, const unsigned* b) {
    asm volatile("mma.sync.aligned.m16n8k16.row.col.f32.bf16.bf16.f32 "
        "{%0,%1,%2,%3}, {%4,%5,%6,%7}, {%8,%9}, {%0,%1,%2,%3};"
        : "+f"(c[0]), "+f"(c[1]), "+f"(c[2]), "+f"(c[3])
        : "r"(a[0]), "r"(a[1]), "r"(a[2]), "r"(a[3]), "r"(b[0]), "r"(b[1]));
}

// scalar split store (used for x tiles where reads must stay coalesced)
__device__ __forceinline__ void cvt_store(__nv_bfloat16* t, int row, int k, float v) {
    __nv_bfloat16 h = __float2bfloat16(v);
    t[row * TS + k] = h;
    t[TILE_HALF + row * TS + k] = __float2bfloat16(v - __bfloat162float(h));
}

__device__ __forceinline__ unsigned pack_bf2(float a, float b) {
    __nv_bfloat162 h = __floats2bfloat162_rn(a, b);
    return *(unsigned*)&h;
}

// vectorized fp32 smem (stride HS) -> split bf16 tile
__device__ __forceinline__ void cvt_tile_vec(__nv_bfloat16* t, const float* src, int tid) {
    for (int idx = tid; idx < 4096; idx += NT) {
        int r = idx >> 5, kg = (idx & 31) << 2;
        float4 v = *(const float4*)(src + r * HS + kg);
        unsigned h01 = pack_bf2(v.x, v.y);
        unsigned h23 = pack_bf2(v.z, v.w);
        __nv_bfloat162 hh01 = *(__nv_bfloat162*)&h01;
        __nv_bfloat162 hh23 = *(__nv_bfloat162*)&h23;
        unsigned l01 = pack_bf2(v.x - __bfloat162float(hh01.x), v.y - __bfloat162float(hh01.y));
        unsigned l23 = pack_bf2(v.z - __bfloat162float(hh23.x), v.w - __bfloat162float(hh23.y));
        *(uint2*)(t + r * TS + kg) = make_uint2(h01, h23);
        *(uint2*)(t + TILE_HALF + r * TS + kg) = make_uint2(l01, l23);
    }
}

// straight 16B copy of a precomputed weight tile global->smem
__device__ __forceinline__ void copy_tile(__nv_bfloat16* dst, const __nv_bfloat16* src, int tid) {
    uint4* d = (uint4*)dst;
    const uint4* s = (const uint4*)src;
    for (int i = tid; i < 4352; i += NT) d[i] = s[i];
}

// per-warp 32x32 GEMM over K=128 (3-term bf16 split)
__device__ __forceinline__ void warp_gemm(const __nv_bfloat16* tA, const __nv_bfloat16* tB,
                                          float acc[2][4][4], int m0, int n0,
                                          int l4, int kq) {
#pragma unroll 2
    for (int ks = 0; ks < 8; ks++) {
        int k0 = ks * 16 + kq;
        unsigned ah[2][4], al[2][4], bh[4][2], bl[4][2];
#pragma unroll
        for (int mb = 0; mb < 2; mb++) {
            const __nv_bfloat16* p = tA + (m0 + mb * 16 + l4) * TS + k0;
            ah[mb][0] = *(const unsigned*)(p);
            ah[mb][1] = *(const unsigned*)(p + 8 * TS);
            ah[mb][2] = *(const unsigned*)(p + 8);
            ah[mb][3] = *(const unsigned*)(p + 8 * TS + 8);
            al[mb][0] = *(const unsigned*)(p + TILE_HALF);
            al[mb][1] = *(const unsigned*)(p + TILE_HALF + 8 * TS);
            al[mb][2] = *(const unsigned*)(p + TILE_HALF + 8);
            al[mb][3] = *(const unsigned*)(p + TILE_HALF + 8 * TS + 8);
        }
#pragma unroll
        for (int nb = 0; nb < 4; nb++) {
            const __nv_bfloat16* p = tB + (n0 + nb * 8 + l4) * TS + k0;
            bh[nb][0] = *(const unsigned*)(p);
            bh[nb][1] = *(const unsigned*)(p + 8);
            bl[nb][0] = *(const unsigned*)(p + TILE_HALF);
            bl[nb][1] = *(const unsigned*)(p + TILE_HALF + 8);
        }
#pragma unroll
        for (int mb = 0; mb < 2; mb++)
#pragma unroll
            for (int nb = 0; nb < 4; nb++) {
                mma_bf16(acc[mb][nb], ah[mb], bh[nb]);
                mma_bf16(acc[mb][nb], ah[mb], bl[nb]);
                mma_bf16(acc[mb][nb], al[mb], bh[nb]);
            }
    }
}

// ---------------- weight tile prep (runs once per launch, 8 blocks) ----------------
__global__ void __launch_bounds__(512) k_prep(const float* __restrict__ embW,
                                              const float* __restrict__ WlA,
                                              const float* __restrict__ WrA,
                                              const float* __restrict__ pW) {
    int t = blockIdx.x, tid = threadIdx.x;
    __nv_bfloat16* dst = g_wt[t];
    for (int idx = tid; idx < 16384; idx += 512) {
        int row = idx >> 7, k = idx & 127;
        float v;
        if (t < 2) {
            v = embW[(size_t)(t * 128 + k) * HIDn + row];        // B[j=row][l=k]
        } else if (t < 6) {
            int u = t - 2;
            const float* W = ((u & 1) ? WrA : WlA) + (u >> 1) * HIDn * HIDn;
            v = W[(size_t)k * HIDn + row];                       // B[j_out=row][j_in=k]
        } else {
            v = pW[(size_t)k * Ln + (t - 6) * 128 + row];        // A[l'=row][j=k]
        }
        __nv_bfloat16 h = __float2bfloat16(v);
        dst[row * TS + k] = h;
        dst[TILE_HALF + row * TS + k] = __float2bfloat16(v - __bfloat162float(h));
    }
}

// ---------------- single-kernel CSR build ----------------
__global__ void k_csr(const void* ei, int E) {
    __shared__ int cnt[Cn];
    __shared__ int base[Cn + 1];
    __shared__ int is64s;
    int tid = threadIdx.x;
    if (tid < 32) {
        int v = ((const int*)ei)[tid * 2 + 1];
        unsigned ball = __ballot_sync(0xffffffffu, v != 0);
        if (tid == 0) is64s = (ball == 0) ? 1 : 0;
    }
    if (tid < Cn) cnt[tid] = 1;
    __syncthreads();
    int is64 = is64s;
    for (int e = tid; e < E; e += blockDim.x) {
        int d = is64 ? (int)((const long long*)ei)[E + e] : ((const int*)ei)[E + e];
        atomicAdd(&cnt[d], 1);
    }
    __syncthreads();
    if (tid < 32) {
        int c0 = cnt[tid*4], c1 = cnt[tid*4+1], c2 = cnt[tid*4+2], c3 = cnt[tid*4+3];
        int s = c0 + c1 + c2 + c3;
        int pre = s;
#pragma unroll
        for (int off = 1; off < 32; off <<= 1) {
            int t = __shfl_up_sync(0xffffffffu, pre, off);
            if (tid >= off) pre += t;
        }
        int excl = pre - s;
        base[tid*4] = excl; base[tid*4+1] = excl + c0;
        base[tid*4+2] = excl + c0 + c1; base[tid*4+3] = excl + c0 + c1 + c2;
        if (tid == 31) base[Cn] = pre;
    }
    __syncthreads();
    if (tid <= Cn) g_ptr[tid] = base[tid];
    if (tid < Cn) cnt[tid] = base[tid];
    __syncthreads();
    for (int e = tid; e < E; e += blockDim.x) {
        int s = is64 ? (int)((const long long*)ei)[e]     : ((const int*)ei)[e];
        int d = is64 ? (int)((const long long*)ei)[E + e] : ((const int*)ei)[E + e];
        int p = atomicAdd(&cnt[d], 1);
        g_src[p] = (unsigned short)s;
    }
    __syncthreads();
    if (tid < Cn) {
        int p = atomicAdd(&cnt[tid], 1);
        g_src[p] = (unsigned short)tid;
    }
}

// ---------------- GAT layer ----------------
template <bool ATT>
__device__ __forceinline__ void gat_layer(
    float* hs, float* xls, float* xrs,
    __nv_bfloat16* tA, __nv_bfloat16* tB, float* rowbuf,
    const int* sptr, const unsigned short* ssrc,
    const __nv_bfloat16* gWl, const __nv_bfloat16* gWr,
    const float* __restrict__ bl, const float* __restrict__ br,
    const float* __restrict__ att, const float* __restrict__ gbias,
    const float* __restrict__ gamma, const float* __restrict__ beta,
    float* attn_rows, int tid) {

    int warp = tid >> 5, lane = tid & 31;
    int l4 = lane >> 2, kq = 2 * (lane & 3);
    int m0 = (warp & 3) * 32, n0 = (warp >> 2) * 32;

    // A <- hs (vectorized split), B <- precomputed Wl tile
    cvt_tile_vec(tA, hs, tid);
    copy_tile(tB, gWl, tid);
    __syncthreads();

    float accL[2][4][4], accR[2][4][4];
#pragma unroll
    for (int mb = 0; mb < 2; mb++)
#pragma unroll
        for (int nb = 0; nb < 4; nb++)
#pragma unroll
            for (int i = 0; i < 4; i++) { accL[mb][nb][i] = 0.f; accR[mb][nb][i] = 0.f; }

    warp_gemm(tA, tB, accL, m0, n0, l4, kq);
    __syncthreads();
    copy_tile(tB, gWr, tid);
    __syncthreads();
    warp_gemm(tA, tB, accR, m0, n0, l4, kq);
    __syncthreads();   // tiles consumed -> xls/xrs may overwrite

#pragma unroll
    for (int mb = 0; mb < 2; mb++)
#pragma unroll
        for (int nb = 0; nb < 4; nb++) {
            int row = m0 + mb * 16 + l4;
            int col = n0 + nb * 8 + kq;
            float2 bl2 = *(const float2*)(bl + col);
            float2 br2 = *(const float2*)(br + col);
            float2 v;
            v.x = accL[mb][nb][0] + bl2.x; v.y = accL[mb][nb][1] + bl2.y;
            *(float2*)(xls + row * HS + col) = v;
            v.x = accL[mb][nb][2] + bl2.x; v.y = accL[mb][nb][3] + bl2.y;
            *(float2*)(xls + (row + 8) * HS + col) = v;
            v.x = accR[mb][nb][0] + br2.x; v.y = accR[mb][nb][1] + br2.y;
            *(float2*)(xrs + row * HS + col) = v;
            v.x = accR[mb][nb][2] + br2.x; v.y = accR[mb][nb][3] + br2.y;
            *(float2*)(xrs + (row + 8) * HS + col) = v;
        }
    __syncthreads();

    // ---- edge softmax aggregation (fp32) ----
    int hh = lane >> 3;
    int k4 = lane * 4;
    float4 a4 = *(const float4*)(att + hh * 32 + (lane & 7) * 4);
    float* rb = rowbuf + warp * 128;

    for (int c = warp; c < Cn; c += 16) {
        int e0 = sptr[c], e1 = sptr[c + 1];
        float4 xr4 = *(const float4*)(xrs + c * HS + k4);
        float sp = 0.f;
        float4 acc = make_float4(0.f, 0.f, 0.f, 0.f);
#pragma unroll 2
        for (int e = e0; e < e1; e++) {
            int s = ssrc[e];
            float4 x4 = *(const float4*)(xls + s * HS + k4);
            float t0 = x4.x + xr4.x; t0 = t0 > 0.f ? t0 : 0.2f * t0;
            float t1 = x4.y + xr4.y; t1 = t1 > 0.f ? t1 : 0.2f * t1;
            float t2 = x4.z + xr4.z; t2 = t2 > 0.f ? t2 : 0.2f * t2;
            float t3 = x4.w + xr4.w; t3 = t3 > 0.f ? t3 : 0.2f * t3;
            float v = t0 * a4.x + t1 * a4.y + t2 * a4.z + t3 * a4.w;
            v += __shfl_xor_sync(0xffffffffu, v, 1);
            v += __shfl_xor_sync(0xffffffffu, v, 2);
            v += __shfl_xor_sync(0xffffffffu, v, 4);
            float p = __expf(v);
            sp += p;
            acc.x += p * x4.x; acc.y += p * x4.y; acc.z += p * x4.z; acc.w += p * x4.w;
        }
        float inv = 1.0f / (sp + 1e-16f);

        float4 gb4 = *(const float4*)(gbias + k4);
        float4 h4 = *(const float4*)(hs + c * HS + k4);
        float val[4];
        {
            float o;
            o = acc.x * inv + gb4.x; o = o > 0.f ? o : expm1f(o); val[0] = h4.x + o;
            o = acc.y * inv + gb4.y; o = o > 0.f ? o : expm1f(o); val[1] = h4.y + o;
            o = acc.z * inv + gb4.z; o = o > 0.f ? o : expm1f(o); val[2] = h4.z + o;
            o = acc.w * inv + gb4.w; o = o > 0.f ? o : expm1f(o); val[3] = h4.w + o;
        }
        float s1 = val[0] + val[1] + val[2] + val[3];
#pragma unroll
        for (int off = 16; off; off >>= 1) s1 += __shfl_xor_sync(0xffffffffu, s1, off);
        float mu = s1 * (1.0f / 128.0f);
        float d0 = val[0] - mu, d1 = val[1] - mu, d2 = val[2] - mu, d3 = val[3] - mu;
        float s2 = d0 * d0 + d1 * d1 + d2 * d2 + d3 * d3;
#pragma unroll
        for (int off = 16; off; off >>= 1) s2 += __shfl_xor_sync(0xffffffffu, s2, off);
        float rs = rsqrtf(s2 * (1.0f / 128.0f) + 1e-5f);
        float4 g4 = *(const float4*)(gamma + k4);
        float4 be4 = *(const float4*)(beta + k4);
        float4 outv;
        outv.x = d0 * rs * g4.x + be4.x;
        outv.y = d1 * rs * g4.y + be4.y;
        outv.z = d2 * rs * g4.z + be4.z;
        outv.w = d3 * rs * g4.w + be4.w;
        *(float4*)(hs + c * HS + k4) = outv;

        if (ATT) {
            *(float4*)(rb + k4) = make_float4(0.f, 0.f, 0.f, 0.f);
            __syncwarp();
            for (int e = e0; e < e1; e++) {
                int s = ssrc[e];
                float4 x4 = *(const float4*)(xls + s * HS + k4);
                float t0 = x4.x + xr4.x; t0 = t0 > 0.f ? t0 : 0.2f * t0;
                float t1 = x4.y + xr4.y; t1 = t1 > 0.f ? t1 : 0.2f * t1;
                float t2 = x4.z + xr4.z; t2 = t2 > 0.f ? t2 : 0.2f * t2;
                float t3 = x4.w + xr4.w; t3 = t3 > 0.f ? t3 : 0.2f * t3;
                float v = t0 * a4.x + t1 * a4.y + t2 * a4.z + t3 * a4.w;
                v += __shfl_xor_sync(0xffffffffu, v, 1);
                v += __shfl_xor_sync(0xffffffffu, v, 2);
                v += __shfl_xor_sync(0xffffffffu, v, 4);
                float am = __expf(v) * inv;
                am += __shfl_xor_sync(0xffffffffu, am, 8);
                am += __shfl_xor_sync(0xffffffffu, am, 16);
                if (lane == 0) rb[s] += am * 0.25f;
            }
            __syncwarp();
            *(float4*)(attn_rows + (size_t)c * 128 + k4) = *(const float4*)(rb + k4);
        }
    }
    __syncthreads();
}

// ---------------- fully fused kernel ----------------
__global__ void __launch_bounds__(NT, 1) k_fused(
    const float* __restrict__ x,
    const float* __restrict__ embB,
    const float* __restrict__ blA, const float* __restrict__ brA,
    const float* __restrict__ attA, const float* __restrict__ gbA,
    const float* __restrict__ gA, const float* __restrict__ beA,
    const float* __restrict__ pB,
    float* __restrict__ out, int nE) {

    extern __shared__ char sm[];
    float* hs = (float*)sm;                                  // 128x132 fp32 = 67584 B
    char* tiles = sm + 67584;                                // 139264 B
    __nv_bfloat16* tA = (__nv_bfloat16*)tiles;               // hi+lo = 69632 B
    __nv_bfloat16* tB = (__nv_bfloat16*)(tiles + 69632);
    float* xls = (float*)tiles;                              // alias (67584 B)
    float* xrs = (float*)(tiles + 67584);
    float* rowbuf = (float*)(sm + 206848);                   // 8192 B
    int* sptr = (int*)(sm + 215040);                         // 528 B
    unsigned short* ssrc = (unsigned short*)(sm + 215568);   // 8704 B

    int b = blockIdx.x, tid = threadIdx.x;
    int warp = tid >> 5, lane = tid & 31;
    int l4 = lane >> 2, kq = 2 * (lane & 3);
    int m0 = (warp & 3) * 32, n0 = (warp >> 2) * 32;

    for (int i = tid; i <= Cn; i += NT) sptr[i] = g_ptr[i];
    for (int i = tid; i < nE; i += NT) ssrc[i] = g_src[i];

    // ---- embed: hs[c][j] = sum_l x[b][l][c] * embW[l][j] + embB[j]
    {
        float accE[2][4][4];
#pragma unroll
        for (int mb = 0; mb < 2; mb++)
#pragma unroll
            for (int nb = 0; nb < 4; nb++)
#pragma unroll
                for (int i = 0; i < 4; i++) accE[mb][nb][i] = 0.f;

        const float* xb = x + (size_t)b * Ln * Cn;
        for (int chunk = 0; chunk < 2; chunk++) {
            int l0c = chunk * 128;
            for (int idx = tid; idx < 16384; idx += NT) {
                int u = idx >> 7, c = idx & 127;
                cvt_store(tA, c, u, xb[(size_t)(l0c + u) * Cn + c]);  // A[c][l]
            }
            copy_tile(tB, g_wt[chunk], tid);
            __syncthreads();
            warp_gemm(tA, tB, accE, m0, n0, l4, kq);
            __syncthreads();
        }
#pragma unroll
        for (int mb = 0; mb < 2; mb++)
#pragma unroll
            for (int nb = 0; nb < 4; nb++) {
                int row = m0 + mb * 16 + l4;
                int col = n0 + nb * 8 + kq;
                float2 eb2 = *(const float2*)(embB + col);
                float2 v;
                v.x = accE[mb][nb][0] + eb2.x; v.y = accE[mb][nb][1] + eb2.y;
                *(float2*)(hs + row * HS + col) = v;
                v.x = accE[mb][nb][2] + eb2.x; v.y = accE[mb][nb][3] + eb2.y;
                *(float2*)(hs + (row + 8) * HS + col) = v;
            }
        __syncthreads();
    }

    float* attn = out + (size_t)Bn * Ln * Cn + (size_t)b * Cn * Cn;
    gat_layer<false>(hs, xls, xrs, tA, tB, rowbuf, sptr, ssrc,
                     g_wt[2], g_wt[3], blA, brA, attA, gbA, gA, beA, nullptr, tid);
    gat_layer<true>(hs, xls, xrs, tA, tB, rowbuf, sptr, ssrc,
                    g_wt[4], g_wt[5], blA + HIDn, brA + HIDn,
                    attA + 128, gbA + HIDn, gA + HIDn, beA + HIDn, attn, tid);

    // ---- proj: out[b][l][c] = sum_j hs[c][j] * pW[j][l] + pB[l]
    cvt_tile_vec(tB, hs, tid);           // B[n=c][k=j] = hs[c][j]
    float* outb = out + (size_t)b * Ln * Cn;
    for (int half = 0; half < 2; half++) {
        copy_tile(tA, g_wt[6 + half], tid);   // A[m=l'][k=j]
        __syncthreads();
        float accP[2][4][4];
#pragma unroll
        for (int mb = 0; mb < 2; mb++)
#pragma unroll
            for (int nb = 0; nb < 4; nb++)
#pragma unroll
                for (int i = 0; i < 4; i++) accP[mb][nb][i] = 0.f;
        warp_gemm(tA, tB, accP, m0, n0, l4, kq);
#pragma unroll
        for (int mb = 0; mb < 2; mb++)
#pragma unroll
            for (int nb = 0; nb < 4; nb++) {
                int l = half * 128 + m0 + mb * 16 + l4;
                int c = n0 + nb * 8 + kq;
                float pb0 = pB[l], pb1 = pB[l + 8];
                float2 v;
                v.x = accP[mb][nb][0] + pb0; v.y = accP[mb][nb][1] + pb0;
                *(float2*)(outb + (size_t)l * Cn + c) = v;
                v.x = accP[mb][nb][2] + pb1; v.y = accP[mb][nb][3] + pb1;
                *(float2*)(outb + (size_t)(l + 8) * Cn + c) = v;
            }
        __syncthreads();   // before tA overwrite for half 1
    }
}

// ---------------- launch ----------------
extern "C" void kernel_launch(void* const* d_in, const int* in_sizes, int n_in,
                              void* d_out, int out_size) {
    const float* x    = (const float*)d_in[0];
    const void*  ei   = d_in[1];
    const float* embW = (const float*)d_in[2];
    const float* embB = (const float*)d_in[3];
    const float* WlA  = (const float*)d_in[4];
    const float* blA  = (const float*)d_in[5];
    const float* WrA  = (const float*)d_in[6];
    const float* brA  = (const float*)d_in[7];
    const float* attA = (const float*)d_in[8];
    const float* gbA  = (const float*)d_in[9];
    const float* gA   = (const float*)d_in[10];
    const float* beA  = (const float*)d_in[11];
    const float* pW   = (const float*)d_in[12];
    const float* pB   = (const float*)d_in[13];
    float* out = (float*)d_out;

    int E = in_sizes[1] / 2;
    int nE = E + Cn;
    if (nE > MAXE) nE = MAXE;

    const int SMEM = 224272;

    cudaFuncSetAttribute(k_fused, cudaFuncAttributeMaxDynamicSharedMemorySize, SMEM);

    k_csr<<<1, 256>>>(ei, E);
    k_prep<<<8, 512>>>(embW, WlA, WrA, pW);
    k_fused<<<Bn, NT, SMEM>>>(x, embB, blA, brA, attA, gbA, gA, beA, pB, out, nE);
}